// round 14
// baseline (speedup 1.0000x reference)
#include <cuda_runtime.h>
#include <cuda_fp16.h>
#include <math.h>
#include <stdint.h>

// ---------------- Problem constants ----------------
#define D_MODEL 1024
#define NHEAD   16
#define HDIM    64
#define DFF     4096
#define TM      512
#define TA      512
#define BATCH   32
#define NTOK    (TM * BATCH)   // 16384
#define NBEATS  64
#define LN_EPS  1e-5f

// ---------------- fp32 scratch ----------------
__device__ float g_x1  [NTOK * D_MODEL];
__device__ float g_x2  [NTOK * D_MODEL];
__device__ float g_bias[TM * TA];

// ---------------- fp16 scratch ----------------
__device__ __half g_X  [NTOK * D_MODEL];
__device__ __half g_AU [NTOK * D_MODEL];
__device__ __half g_TMP[NTOK * D_MODEL];
__device__ __half g_H  [NTOK * DFF];
__device__ __half g_QKV[NTOK * 3 * D_MODEL];
__device__ __half g_KV [NTOK * 2 * D_MODEL];
__device__ __half g_CQ [NTOK * D_MODEL];
__device__ __half g_W  [16777216];

#define W_SAIN   0
#define W_SAOUT  3145728
#define W_CAIN   4194304
#define W_CAOUT  7340032
#define W_LIN1   8388608
#define W_LIN2  12582912
#define W_TOTAL 16777216

// ================= helpers (non-'a' PTX only) =================
__device__ __forceinline__ uint32_t smem_u32(const void* p) {
    uint32_t a;
    asm("{ .reg .u64 t; cvta.to.shared.u64 t, %1; cvt.u32.u64 %0, t; }" : "=r"(a) : "l"(p));
    return a;
}
__device__ __forceinline__ void cp_async16(uint32_t saddr, const void* g) {
    asm volatile("cp.async.cg.shared.global [%0], [%1], 16;" :: "r"(saddr), "l"(g));
}
__device__ __forceinline__ void cp_commit() {
    asm volatile("cp.async.commit_group;" ::: "memory");
}
__device__ __forceinline__ void ldsm_x4(uint32_t (&r)[4], uint32_t addr) {
    asm volatile("ldmatrix.sync.aligned.m8n8.x4.shared.b16 {%0,%1,%2,%3}, [%4];"
                 : "=r"(r[0]), "=r"(r[1]), "=r"(r[2]), "=r"(r[3]) : "r"(addr));
}
__device__ __forceinline__ void ldsm_x4_t(uint32_t (&r)[4], uint32_t addr) {
    asm volatile("ldmatrix.sync.aligned.m8n8.x4.trans.shared.b16 {%0,%1,%2,%3}, [%4];"
                 : "=r"(r[0]), "=r"(r[1]), "=r"(r[2]), "=r"(r[3]) : "r"(addr));
}
__device__ __forceinline__ void mma16816(float (&d)[4], const uint32_t (&a)[4],
                                         uint32_t b0, uint32_t b1) {
    asm volatile(
        "mma.sync.aligned.m16n8k16.row.col.f32.f16.f16.f32 "
        "{%0,%1,%2,%3}, {%4,%5,%6,%7}, {%8,%9}, {%0,%1,%2,%3};"
        : "+f"(d[0]), "+f"(d[1]), "+f"(d[2]), "+f"(d[3])
        : "r"(a[0]), "r"(a[1]), "r"(a[2]), "r"(a[3]), "r"(b0), "r"(b1));
}
__device__ __forceinline__ uint32_t pack_h2(float x, float y) {
    return (uint32_t)__half_as_ushort(__float2half_rn(x)) |
           ((uint32_t)__half_as_ushort(__float2half_rn(y)) << 16);
}

// ================= converts =================
// src and audio in ONE launch: blocks [0, nb) -> src, [nb, 2nb) -> audio
__global__ __launch_bounds__(256) void cvt2_kernel(
    const float* __restrict__ s0, __half* __restrict__ d0,
    const float* __restrict__ s1, __half* __restrict__ d1, int nb)
{
    const float* s = s0; __half* d = d0;
    int bx = blockIdx.x;
    if (bx >= nb) { s = s1; d = d1; bx -= nb; }
    int i = (bx * 256 + threadIdx.x) * 4;
    float4 v = *(const float4*)(s + i);
    uint2 uh;
    uh.x = pack_h2(v.x, v.y);
    uh.y = pack_h2(v.z, v.w);
    *(uint2*)(d + i) = uh;
}

__global__ __launch_bounds__(256) void wcvt_kernel(
    const float* __restrict__ w0, const float* __restrict__ w1,
    const float* __restrict__ w2, const float* __restrict__ w3,
    const float* __restrict__ w4, const float* __restrict__ w5,
    __half* __restrict__ hi)
{
    int i = (blockIdx.x * 256 + threadIdx.x) * 4;
    const float* src; int off;
    if      (i < W_SAOUT) { src = w0; off = W_SAIN; }
    else if (i < W_CAIN)  { src = w1; off = W_SAOUT; }
    else if (i < W_CAOUT) { src = w2; off = W_CAIN; }
    else if (i < W_LIN1)  { src = w3; off = W_CAOUT; }
    else if (i < W_LIN2)  { src = w4; off = W_LIN1; }
    else                  { src = w5; off = W_LIN2; }
    float4 v = *(const float4*)(src + (i - off));
    uint2 uh;
    uh.x = pack_h2(v.x, v.y);
    uh.y = pack_h2(v.z, v.w);
    *(uint2*)(hi + i) = uh;
}

// ================= mma.sync GEMM (fp16, BK=64, fp16 out, dual param-set) =================
#define G_STAGE 32768
#define G_SMEM  (3 * G_STAGE)

__global__ __launch_bounds__(256, 2) void gemm_mma(
    const __half* __restrict__ A, const __half* __restrict__ B,
    const float* __restrict__ bias, __half* __restrict__ Oh,
    int N, int K, int act,
    const __half* A2, const __half* B2, const float* bias2,
    __half* Oh2, int N2, int nx1)
{
    extern __shared__ __align__(128) char smem[];
    const uint32_t sbase = smem_u32(smem);
    const int tid = threadIdx.x;
    const int lane = tid & 31, wid = tid >> 5;
    const int warp_m = wid & 3, warp_n = wid >> 2;

    int bx = blockIdx.x;
    if (A2 && bx >= nx1) {
        A = A2; B = B2; bias = bias2; Oh = Oh2; N = N2;
        bx -= nx1;
    }
    const int m0 = blockIdx.y * 128, n0 = bx * 128;

    float acc[2][8][4];
    #pragma unroll
    for (int t = 0; t < 2; t++)
        #pragma unroll
        for (int j = 0; j < 8; j++)
            #pragma unroll
            for (int e = 0; e < 4; e++) acc[t][j][e] = 0.0f;

    auto stage_load = [&](int ci, int st) {
        const uint32_t sb = sbase + st * G_STAGE;
        const int kk = ci * 64;
        #pragma unroll
        for (int it = 0; it < 4; it++) {
            int idx = tid + it * 256;
            int r = idx >> 3, c = idx & 7;
            uint32_t sw = r * 128 + ((c ^ (r & 7)) << 4);
            cp_async16(sb + sw, A + (size_t)(m0 + r) * K + kk + c * 8);
        }
        #pragma unroll
        for (int it = 0; it < 4; it++) {
            int idx = tid + it * 256;
            int r = idx >> 3, c = idx & 7;
            uint32_t sw = r * 128 + ((c ^ (r & 7)) << 4);
            cp_async16(sb + 16384 + sw, B + (size_t)(n0 + r) * K + kk + c * 8);
        }
        cp_commit();
    };

    const int lr = lane & 15;
    const int lseg = lane >> 4;
    int arow[2], brow[4];
    #pragma unroll
    for (int t = 0; t < 2; t++) arow[t] = warp_m * 32 + t * 16 + lr;
    #pragma unroll
    for (int u = 0; u < 4; u++) brow[u] = warp_n * 64 + u * 16 + lr;

    const int nch = K >> 6;
    stage_load(0, 0);
    stage_load(1, 1);

    for (int i = 0; i < nch; i++) {
        if (i < nch - 1) asm volatile("cp.async.wait_group 1;" ::: "memory");
        else             asm volatile("cp.async.wait_group 0;" ::: "memory");
        __syncthreads();
        if (i + 2 < nch) stage_load(i + 2, (i + 2) % 3);

        const uint32_t sb = sbase + (i % 3) * G_STAGE;
        #pragma unroll
        for (int kc = 0; kc < 4; kc++) {
            const int chunk = 2 * kc + lseg;
            uint32_t ah[2][4], bh[4][4];
            #pragma unroll
            for (int t = 0; t < 2; t++) {
                uint32_t a = sb + arow[t] * 128 + ((chunk ^ (arow[t] & 7)) << 4);
                ldsm_x4(ah[t], a);
            }
            #pragma unroll
            for (int u = 0; u < 4; u++) {
                uint32_t a = sb + 16384 + brow[u] * 128 + ((chunk ^ (brow[u] & 7)) << 4);
                ldsm_x4(bh[u], a);
            }
            #pragma unroll
            for (int t = 0; t < 2; t++)
                #pragma unroll
                for (int u = 0; u < 4; u++) {
                    mma16816(acc[t][2 * u],     ah[t], bh[u][0], bh[u][2]);
                    mma16816(acc[t][2 * u + 1], ah[t], bh[u][1], bh[u][3]);
                }
        }
    }

    #pragma unroll
    for (int t = 0; t < 2; t++) {
        const int rbase = m0 + warp_m * 32 + t * 16 + (lane >> 2);
        #pragma unroll
        for (int j = 0; j < 8; j++) {
            const int col = n0 + warp_n * 64 + j * 8 + 2 * (lane & 3);
            const float b0 = __ldg(bias + col), b1 = __ldg(bias + col + 1);
            #pragma unroll
            for (int half = 0; half < 2; half++) {
                const int row = rbase + 8 * half;
                float v0 = acc[t][j][2 * half]     + b0;
                float v1 = acc[t][j][2 * half + 1] + b1;
                if (act) {
                    v0 = 0.5f * v0 * (1.0f + erff(v0 * 0.70710678118654752f));
                    v1 = 0.5f * v1 * (1.0f + erff(v1 * 0.70710678118654752f));
                }
                *(uint32_t*)(Oh + (size_t)row * N + col) = pack_h2(v0, v1);
            }
        }
    }
}

// ================= FA2-style attention (fp16, 128-query blocks) =================
// 256 threads / 8 warps; warp w owns q-rows w*16..w*16+15 of a 128-query tile.
// K/V tiles (64 keys) shared by all 8 warps -> half the global traffic of the
// 64-query version. Buffers: K@0 (8K), V@8K; 3 stages x 16KB.
#define AT_BUF  16384
#define AT_SMEM (3 * AT_BUF)

__global__ __launch_bounds__(256) void attn_mma(
    const __half* __restrict__ Q, int ldq, int qoff,
    const __half* __restrict__ Kb, int ldk, int koff,
    const __half* __restrict__ Vb, int ldv, int voff,
    __half* __restrict__ Oh,
    const float* __restrict__ bias, float scale)
{
    extern __shared__ __align__(128) char smem[];
    const uint32_t sbase = smem_u32(smem);
    const int tid = threadIdx.x, lane = tid & 31, w = tid >> 5;
    const int qt = blockIdx.x, bh = blockIdx.y;
    const int b = bh & (BATCH - 1), h = bh >> 5;

    // stage Q (128 rows x 128B = 16KB) into buffer 0, grab fragments, release
    #pragma unroll
    for (int it = 0; it < 4; it++) {
        int idx = tid + it * 256, r = idx >> 3, c = idx & 7;
        uint32_t sw = r * 128 + ((c ^ (r & 7)) << 4);
        size_t g = (size_t)((qt * 128 + r) * BATCH + b) * ldq + qoff + h * HDIM + c * 8;
        cp_async16(sbase + sw, Q + g);
    }
    cp_commit();
    asm volatile("cp.async.wait_group 0;" ::: "memory");
    __syncthreads();

    const int lr = lane & 15, ls = lane >> 4;
    uint32_t qh[4][4];
    {
        int qrow = w * 16 + lr;
        #pragma unroll
        for (int kc = 0; kc < 4; kc++) {
            int chunk = 2 * kc + ls;
            uint32_t a = sbase + qrow * 128 + ((chunk ^ (qrow & 7)) << 4);
            ldsm_x4(qh[kc], a);
        }
    }
    __syncthreads();

    auto load_kt = [&](int kt, int st) {
        uint32_t sb = sbase + st * AT_BUF;
        #pragma unroll
        for (int it = 0; it < 2; it++) {
            int idx = tid + it * 256, r = idx >> 3, c = idx & 7;
            uint32_t sw = r * 128 + ((c ^ (r & 7)) << 4);
            size_t rowi = (size_t)((kt * 64 + r) * BATCH + b);
            cp_async16(sb + sw,        Kb + rowi * ldk + koff + h * HDIM + c * 8);
            cp_async16(sb + 8192 + sw, Vb + rowi * ldv + voff + h * HDIM + c * 8);
        }
        cp_commit();
    };
    load_kt(0, 0);
    load_kt(1, 1);

    float o[8][4];
    #pragma unroll
    for (int t = 0; t < 8; t++)
        #pragma unroll
        for (int e = 0; e < 4; e++) o[t][e] = 0.0f;
    float mrow0 = -1e30f, mrow1 = -1e30f, lsum0 = 0.0f, lsum1 = 0.0f;

    const int vkbase = ((lane & 16) ? 8 : 0) + (lane & 7);
    const int vcsel  = (lane >> 3) & 1;

    for (int kt = 0; kt < 8; kt++) {
        if (kt < 7) asm volatile("cp.async.wait_group 1;" ::: "memory");
        else        asm volatile("cp.async.wait_group 0;" ::: "memory");
        __syncthreads();
        if (kt + 2 < 8) load_kt(kt + 2, (kt + 2) % 3);
        const uint32_t sb = sbase + (kt % 3) * AT_BUF;

        float s[8][4];
        #pragma unroll
        for (int t = 0; t < 8; t++)
            #pragma unroll
            for (int e = 0; e < 4; e++) s[t][e] = 0.0f;
        #pragma unroll
        for (int kc = 0; kc < 4; kc++) {
            uint32_t kh[4][4];
            #pragma unroll
            for (int u = 0; u < 4; u++) {
                int krow = u * 16 + lr, chunk = 2 * kc + ls;
                uint32_t a = sb + krow * 128 + ((chunk ^ (krow & 7)) << 4);
                ldsm_x4(kh[u], a);
            }
            #pragma unroll
            for (int u = 0; u < 4; u++) {
                mma16816(s[2 * u],     qh[kc], kh[u][0], kh[u][2]);
                mma16816(s[2 * u + 1], qh[kc], kh[u][1], kh[u][3]);
            }
        }

        const int row0 = qt * 128 + w * 16 + (lane >> 2);
        if (bias) {
            #pragma unroll
            for (int t = 0; t < 8; t++) {
                int col = kt * 64 + t * 8 + 2 * (lane & 3);
                float2 b0 = *(const float2*)(bias + (size_t)row0 * TA + col);
                float2 b1 = *(const float2*)(bias + (size_t)(row0 + 8) * TA + col);
                s[t][0] = s[t][0] * scale + b0.x; s[t][1] = s[t][1] * scale + b0.y;
                s[t][2] = s[t][2] * scale + b1.x; s[t][3] = s[t][3] * scale + b1.y;
            }
        } else {
            #pragma unroll
            for (int t = 0; t < 8; t++)
                #pragma unroll
                for (int e = 0; e < 4; e++) s[t][e] *= scale;
        }

        float mx0 = -1e30f, mx1 = -1e30f;
        #pragma unroll
        for (int t = 0; t < 8; t++) {
            mx0 = fmaxf(mx0, fmaxf(s[t][0], s[t][1]));
            mx1 = fmaxf(mx1, fmaxf(s[t][2], s[t][3]));
        }
        mx0 = fmaxf(mx0, __shfl_xor_sync(0xffffffffu, mx0, 1));
        mx0 = fmaxf(mx0, __shfl_xor_sync(0xffffffffu, mx0, 2));
        mx1 = fmaxf(mx1, __shfl_xor_sync(0xffffffffu, mx1, 1));
        mx1 = fmaxf(mx1, __shfl_xor_sync(0xffffffffu, mx1, 2));
        float mn0 = fmaxf(mrow0, mx0), mn1 = fmaxf(mrow1, mx1);
        float a0 = __expf(mrow0 - mn0), a1 = __expf(mrow1 - mn1);
        mrow0 = mn0; mrow1 = mn1;

        float sum0 = 0.0f, sum1 = 0.0f;
        uint32_t phi[4][4];
        #pragma unroll
        for (int t = 0; t < 8; t++) {
            float p0 = __expf(s[t][0] - mn0), p1 = __expf(s[t][1] - mn0);
            float p2 = __expf(s[t][2] - mn1), p3 = __expf(s[t][3] - mn1);
            sum0 += p0 + p1; sum1 += p2 + p3;
            const int kc = t >> 1, j = (t & 1) * 2;
            phi[kc][j]     = pack_h2(p0, p1);
            phi[kc][j + 1] = pack_h2(p2, p3);
        }
        sum0 += __shfl_xor_sync(0xffffffffu, sum0, 1);
        sum0 += __shfl_xor_sync(0xffffffffu, sum0, 2);
        sum1 += __shfl_xor_sync(0xffffffffu, sum1, 1);
        sum1 += __shfl_xor_sync(0xffffffffu, sum1, 2);
        lsum0 = lsum0 * a0 + sum0;
        lsum1 = lsum1 * a1 + sum1;
        #pragma unroll
        for (int t = 0; t < 8; t++) {
            o[t][0] *= a0; o[t][1] *= a0;
            o[t][2] *= a1; o[t][3] *= a1;
        }

        #pragma unroll
        for (int kc = 0; kc < 4; kc++) {
            int vkey = kc * 16 + vkbase;
            uint32_t vh[4][4];
            #pragma unroll
            for (int du = 0; du < 4; du++) {
                int chunk = 2 * du + vcsel;
                uint32_t a = sb + 8192 + vkey * 128 + ((chunk ^ (vkey & 7)) << 4);
                ldsm_x4_t(vh[du], a);
            }
            #pragma unroll
            for (int du = 0; du < 4; du++) {
                mma16816(o[2 * du],     phi[kc], vh[du][0], vh[du][2]);
                mma16816(o[2 * du + 1], phi[kc], vh[du][1], vh[du][3]);
            }
        }
    }

    float inv0 = 1.0f / lsum0, inv1 = 1.0f / lsum1;
    const int row0 = qt * 128 + w * 16 + (lane >> 2);
    #pragma unroll
    for (int t = 0; t < 8; t++) {
        int col = t * 8 + 2 * (lane & 3);
        size_t off0 = (size_t)(row0 * BATCH + b) * D_MODEL + h * HDIM + col;
        size_t off1 = (size_t)((row0 + 8) * BATCH + b) * D_MODEL + h * HDIM + col;
        *(uint32_t*)(Oh + off0) = pack_h2(o[t][0] * inv0, o[t][1] * inv0);
        *(uint32_t*)(Oh + off1) = pack_h2(o[t][2] * inv1, o[t][3] * inv1);
    }
}

// ---------------- Bias precompute ----------------
__global__ void bias_kernel(const int* __restrict__ beats, float* __restrict__ out) {
    __shared__ int sb[NBEATS];
    int i = blockIdx.x;
    int j = threadIdx.x;
    if (threadIdx.x < NBEATS) sb[threadIdx.x] = beats[threadIdx.x];
    __syncthreads();
    float bb = 0.0f;
    #pragma unroll 8
    for (int n = 0; n < NBEATS; n++) {
        int bf = sb[n];
        if (j == bf) bb = fmaxf(bb, 2.0f);
        if (bf > 0      && j == bf - 1) bb = fmaxf(bb, 1.0f);
        if (bf < TA - 1 && j == bf + 1) bb = fmaxf(bb, 1.0f);
    }
    float scale = (float)(TA - 1) / (float)(TM - 1);
    float d = (float)i * scale - (float)j;
    out[i * TA + j] = -(d * d) * (1.0f / 32.0f) + bb;
}

// ---------------- Fused residual + LayerNorm ----------------
__global__ __launch_bounds__(256) void add_ln_kernel(
    const float* __restrict__ A, const __half* __restrict__ Bv,
    const float* __restrict__ gatePtr,
    const float* __restrict__ gamma, const float* __restrict__ beta,
    float* __restrict__ out, __half* __restrict__ oh)
{
    int t = blockIdx.x;
    int tid = threadIdx.x;
    float gscale = gatePtr ? tanhf(*gatePtr) : 1.0f;
    const float4* a4 = (const float4*)(A + (size_t)t * D_MODEL);
    const uint2*  b2 = (const uint2*)(Bv + (size_t)t * D_MODEL);
    float4 av = a4[tid];
    uint2 ub = b2[tid];
    __half2 h01 = *(__half2*)&ub.x;
    __half2 h23 = *(__half2*)&ub.y;
    float x0 = av.x + gscale * __low2float(h01);
    float x1 = av.y + gscale * __high2float(h01);
    float x2 = av.z + gscale * __low2float(h23);
    float x3 = av.w + gscale * __high2float(h23);
    float s  = x0 + x1 + x2 + x3;
    float ss = x0 * x0 + x1 * x1 + x2 * x2 + x3 * x3;

    __shared__ float rs[8], rss[8];
    #pragma unroll
    for (int o = 16; o > 0; o >>= 1) {
        s  += __shfl_xor_sync(0xffffffffu, s,  o);
        ss += __shfl_xor_sync(0xffffffffu, ss, o);
    }
    if ((tid & 31) == 0) { rs[tid >> 5] = s; rss[tid >> 5] = ss; }
    __syncthreads();
    float stot = 0.0f, sstot = 0.0f;
    #pragma unroll
    for (int i = 0; i < 8; i++) { stot += rs[i]; sstot += rss[i]; }
    float mean = stot * (1.0f / D_MODEL);
    float var  = sstot * (1.0f / D_MODEL) - mean * mean;
    float rstd = rsqrtf(var + LN_EPS);

    const float4* g4 = (const float4*)gamma;
    const float4* be4 = (const float4*)beta;
    float4 g = g4[tid], be = be4[tid];
    float4 o;
    o.x = (x0 - mean) * rstd * g.x + be.x;
    o.y = (x1 - mean) * rstd * g.y + be.y;
    o.z = (x2 - mean) * rstd * g.z + be.z;
    o.w = (x3 - mean) * rstd * g.w + be.w;
    ((float4*)(out + (size_t)t * D_MODEL))[tid] = o;
    if (oh) {
        uint2 uh;
        uh.x = pack_h2(o.x, o.y);
        uh.y = pack_h2(o.z, o.w);
        ((uint2*)(oh + (size_t)t * D_MODEL))[tid] = uh;
    }
}

// ---------------- Launch ----------------
extern "C" void kernel_launch(void* const* d_in, const int* in_sizes, int n_in,
                              void* d_out, int out_size) {
    const float* src      = (const float*)d_in[0];
    const float* audio    = (const float*)d_in[1];
    const int*   beats    = (const int*)  d_in[2];
    const float* sa_in_w  = (const float*)d_in[3];
    const float* sa_in_b  = (const float*)d_in[4];
    const float* sa_out_w = (const float*)d_in[5];
    const float* sa_out_b = (const float*)d_in[6];
    const float* ca_in_w  = (const float*)d_in[7];
    const float* ca_in_b  = (const float*)d_in[8];
    const float* ca_out_w = (const float*)d_in[9];
    const float* ca_out_b = (const float*)d_in[10];
    const float* gate     = (const float*)d_in[11];
    const float* n1_g     = (const float*)d_in[12];
    const float* n1_b     = (const float*)d_in[13];
    const float* nc_g     = (const float*)d_in[14];
    const float* nc_b     = (const float*)d_in[15];
    const float* n2_g     = (const float*)d_in[16];
    const float* n2_b     = (const float*)d_in[17];
    const float* lin1_w   = (const float*)d_in[18];
    const float* lin1_b   = (const float*)d_in[19];
    const float* lin2_w   = (const float*)d_in[20];
    const float* lin2_b   = (const float*)d_in[21];
    float* out = (float*)d_out;

    float *x1, *x2, *bias;
    __half *X, *AU, *TMP, *H, *W, *QKV, *KV, *CQ;
    cudaGetSymbolAddress((void**)&x1,   g_x1);
    cudaGetSymbolAddress((void**)&x2,   g_x2);
    cudaGetSymbolAddress((void**)&bias, g_bias);
    cudaGetSymbolAddress((void**)&X,    g_X);
    cudaGetSymbolAddress((void**)&AU,   g_AU);
    cudaGetSymbolAddress((void**)&TMP,  g_TMP);
    cudaGetSymbolAddress((void**)&H,    g_H);
    cudaGetSymbolAddress((void**)&W,    g_W);
    cudaGetSymbolAddress((void**)&QKV,  g_QKV);
    cudaGetSymbolAddress((void**)&KV,   g_KV);
    cudaGetSymbolAddress((void**)&CQ,   g_CQ);

    cudaFuncSetAttribute(gemm_mma, cudaFuncAttributeMaxDynamicSharedMemorySize, G_SMEM);
    cudaFuncSetAttribute(attn_mma, cudaFuncAttributeMaxDynamicSharedMemorySize, AT_SMEM);

    const int CVT_B = 256 * 4;
    #define H_NULL (__half*)nullptr
    #define GEMM1(a, bw, bp, oh, Nn, Kk, act) \
        gemm_mma<<<dim3((Nn) / 128, NTOK / 128), 256, G_SMEM>>>( \
            a, bw, bp, oh, Nn, Kk, act, H_NULL, H_NULL, nullptr, H_NULL, 0, 0)

    // 0-2) bias, weights, src+audio converts (fused)
    bias_kernel<<<TM, TA>>>(beats, bias);
    wcvt_kernel<<<W_TOTAL / CVT_B, 256>>>(sa_in_w, sa_out_w, ca_in_w, ca_out_w,
                                          lin1_w, lin2_w, W);
    {
        const int nb = NTOK * D_MODEL / CVT_B;
        cvt2_kernel<<<2 * nb, 256>>>(src, X, audio, AU, nb);
    }

    // 3) fused: SA packed QKV (24 tiles) + CA KV-proj (16 tiles)
    gemm_mma<<<dim3(40, NTOK / 128), 256, G_SMEM>>>(
        X, W + W_SAIN, sa_in_b, QKV, 3 * D_MODEL, D_MODEL, 0,
        AU, W + W_CAIN + (size_t)D_MODEL * D_MODEL, ca_in_b + D_MODEL,
        KV, 2 * D_MODEL, 24);

    // 4) SA attention (128-query blocks)
    attn_mma<<<dim3(TM / 128, BATCH * NHEAD), 256, AT_SMEM>>>(
        QKV, 3 * D_MODEL, 0,
        QKV, 3 * D_MODEL, D_MODEL,
        QKV, 3 * D_MODEL, 2 * D_MODEL,
        X, nullptr, 0.125f);

    // 5) SA out-proj (fp16 out)
    GEMM1(X, W + W_SAOUT, sa_out_b, TMP, D_MODEL, D_MODEL, 0);

    // 6) x1 = LN1(src + sa), fused fp16 out
    add_ln_kernel<<<NTOK, 256>>>(src, TMP, nullptr, n1_g, n1_b, x1, X);

    // 7) CA Q-proj
    GEMM1(X, W + W_CAIN, ca_in_b, CQ, D_MODEL, D_MODEL, 0);

    // 8) CA attention (biased)
    attn_mma<<<dim3(TM / 128, BATCH * NHEAD), 256, AT_SMEM>>>(
        CQ, D_MODEL, 0,
        KV, 2 * D_MODEL, 0,
        KV, 2 * D_MODEL, D_MODEL,
        X, bias, 0.125f);

    // 9) CA out-proj (fp16 out)
    GEMM1(X, W + W_CAOUT, ca_out_b, TMP, D_MODEL, D_MODEL, 0);

    // 10) x2 = LNc(x1 + tanh(gate)*cross), fused fp16 out
    add_ln_kernel<<<NTOK, 256>>>(x1, TMP, gate, nc_g, nc_b, x2, X);

    // 11-12) FFN
    GEMM1(X, W + W_LIN1, lin1_b, H, DFF, D_MODEL, 1);
    GEMM1(H, W + W_LIN2, lin2_b, TMP, D_MODEL, DFF, 0);

    // 13) out = LN2(x2 + ff)
    add_ln_kernel<<<NTOK, 256>>>(x2, TMP, nullptr, n2_g, n2_b, out, H_NULL);
}

// round 15
// speedup vs baseline: 1.0042x; 1.0042x over previous
#include <cuda_runtime.h>
#include <cuda_fp16.h>
#include <math.h>
#include <stdint.h>

// ---------------- Problem constants ----------------
#define D_MODEL 1024
#define NHEAD   16
#define HDIM    64
#define DFF     4096
#define TM      512
#define TA      512
#define BATCH   32
#define NTOK    (TM * BATCH)   // 16384
#define NBEATS  64
#define LN_EPS  1e-5f

// ---------------- fp32 scratch ----------------
__device__ float g_x1  [NTOK * D_MODEL];
__device__ float g_x2  [NTOK * D_MODEL];
__device__ float g_bias[TM * TA];

// ---------------- fp16 scratch ----------------
__device__ __half g_X  [NTOK * D_MODEL];
__device__ __half g_AU [NTOK * D_MODEL];
__device__ __half g_TMP[NTOK * D_MODEL];
__device__ __half g_H  [NTOK * DFF];
__device__ __half g_QKV[NTOK * 3 * D_MODEL];
__device__ __half g_KV [NTOK * 2 * D_MODEL];
__device__ __half g_CQ [NTOK * D_MODEL];
__device__ __half g_W  [16777216];

#define W_SAIN   0
#define W_SAOUT  3145728
#define W_CAIN   4194304
#define W_CAOUT  7340032
#define W_LIN1   8388608
#define W_LIN2  12582912
#define W_TOTAL 16777216

// ================= helpers (non-'a' PTX only) =================
__device__ __forceinline__ uint32_t smem_u32(const void* p) {
    uint32_t a;
    asm("{ .reg .u64 t; cvta.to.shared.u64 t, %1; cvt.u32.u64 %0, t; }" : "=r"(a) : "l"(p));
    return a;
}
__device__ __forceinline__ void cp_async16(uint32_t saddr, const void* g) {
    asm volatile("cp.async.cg.shared.global [%0], [%1], 16;" :: "r"(saddr), "l"(g));
}
__device__ __forceinline__ void cp_commit() {
    asm volatile("cp.async.commit_group;" ::: "memory");
}
__device__ __forceinline__ void ldsm_x4(uint32_t (&r)[4], uint32_t addr) {
    asm volatile("ldmatrix.sync.aligned.m8n8.x4.shared.b16 {%0,%1,%2,%3}, [%4];"
                 : "=r"(r[0]), "=r"(r[1]), "=r"(r[2]), "=r"(r[3]) : "r"(addr));
}
__device__ __forceinline__ void ldsm_x4_t(uint32_t (&r)[4], uint32_t addr) {
    asm volatile("ldmatrix.sync.aligned.m8n8.x4.trans.shared.b16 {%0,%1,%2,%3}, [%4];"
                 : "=r"(r[0]), "=r"(r[1]), "=r"(r[2]), "=r"(r[3]) : "r"(addr));
}
__device__ __forceinline__ void mma16816(float (&d)[4], const uint32_t (&a)[4],
                                         uint32_t b0, uint32_t b1) {
    asm volatile(
        "mma.sync.aligned.m16n8k16.row.col.f32.f16.f16.f32 "
        "{%0,%1,%2,%3}, {%4,%5,%6,%7}, {%8,%9}, {%0,%1,%2,%3};"
        : "+f"(d[0]), "+f"(d[1]), "+f"(d[2]), "+f"(d[3])
        : "r"(a[0]), "r"(a[1]), "r"(a[2]), "r"(a[3]), "r"(b0), "r"(b1));
}
__device__ __forceinline__ uint32_t pack_h2(float x, float y) {
    return (uint32_t)__half_as_ushort(__float2half_rn(x)) |
           ((uint32_t)__half_as_ushort(__float2half_rn(y)) << 16);
}

// ================= converts =================
__global__ __launch_bounds__(256) void cvt2_kernel(
    const float* __restrict__ s0, __half* __restrict__ d0,
    const float* __restrict__ s1, __half* __restrict__ d1, int nb)
{
    const float* s = s0; __half* d = d0;
    int bx = blockIdx.x;
    if (bx >= nb) { s = s1; d = d1; bx -= nb; }
    int i = (bx * 256 + threadIdx.x) * 4;
    float4 v = *(const float4*)(s + i);
    uint2 uh;
    uh.x = pack_h2(v.x, v.y);
    uh.y = pack_h2(v.z, v.w);
    *(uint2*)(d + i) = uh;
}

__global__ __launch_bounds__(256) void wcvt_kernel(
    const float* __restrict__ w0, const float* __restrict__ w1,
    const float* __restrict__ w2, const float* __restrict__ w3,
    const float* __restrict__ w4, const float* __restrict__ w5,
    __half* __restrict__ hi)
{
    int i = (blockIdx.x * 256 + threadIdx.x) * 4;
    const float* src; int off;
    if      (i < W_SAOUT) { src = w0; off = W_SAIN; }
    else if (i < W_CAIN)  { src = w1; off = W_SAOUT; }
    else if (i < W_CAOUT) { src = w2; off = W_CAIN; }
    else if (i < W_LIN1)  { src = w3; off = W_CAOUT; }
    else if (i < W_LIN2)  { src = w4; off = W_LIN1; }
    else                  { src = w5; off = W_LIN2; }
    float4 v = *(const float4*)(src + (i - off));
    uint2 uh;
    uh.x = pack_h2(v.x, v.y);
    uh.y = pack_h2(v.z, v.w);
    *(uint2*)(hi + i) = uh;
}

// ================= mma.sync GEMM (fp16, BK=64, fp16 out, dual param-set) =================
// Global pointers + swizzled smem offsets hoisted out of the main loop.
#define G_STAGE 32768
#define G_SMEM  (3 * G_STAGE)

__global__ __launch_bounds__(256, 2) void gemm_mma(
    const __half* __restrict__ A, const __half* __restrict__ B,
    const float* __restrict__ bias, __half* __restrict__ Oh,
    int N, int K, int act,
    const __half* A2, const __half* B2, const float* bias2,
    __half* Oh2, int N2, int nx1)
{
    extern __shared__ __align__(128) char smem[];
    const uint32_t sbase = smem_u32(smem);
    const int tid = threadIdx.x;
    const int lane = tid & 31, wid = tid >> 5;
    const int warp_m = wid & 3, warp_n = wid >> 2;

    int bx = blockIdx.x;
    if (A2 && bx >= nx1) {
        A = A2; B = B2; bias = bias2; Oh = Oh2; N = N2;
        bx -= nx1;
    }
    const int m0 = blockIdx.y * 128, n0 = bx * 128;

    float acc[2][8][4];
    #pragma unroll
    for (int t = 0; t < 2; t++)
        #pragma unroll
        for (int j = 0; j < 8; j++)
            #pragma unroll
            for (int e = 0; e < 4; e++) acc[t][j][e] = 0.0f;

    // ---- hoisted load addressing: thread covers rows tid/8 + 32*it, chunk tid&7
    const int lrr = tid >> 3, lcc = tid & 7;
    uint32_t lsw[4];
    const __half* gA[4];
    const __half* gB[4];
    #pragma unroll
    for (int it = 0; it < 4; it++) {
        int r = lrr + it * 32;
        lsw[it] = r * 128 + ((lcc ^ (r & 7)) << 4);
        gA[it] = A + (size_t)(m0 + r) * K + lcc * 8;
        gB[it] = B + (size_t)(n0 + r) * K + lcc * 8;
    }

    auto stage_load = [&](int kk, int st) {
        const uint32_t sb = sbase + st * G_STAGE;
        #pragma unroll
        for (int it = 0; it < 4; it++)
            cp_async16(sb + lsw[it], gA[it] + kk);
        #pragma unroll
        for (int it = 0; it < 4; it++)
            cp_async16(sb + 16384 + lsw[it], gB[it] + kk);
        cp_commit();
    };

    const int lr = lane & 15;
    const int lseg = lane >> 4;
    // hoisted fragment smem offsets (relative to stage base) per kc
    uint32_t aoff[4][2], boff[4][4];
    #pragma unroll
    for (int kc = 0; kc < 4; kc++) {
        const int chunk = 2 * kc + lseg;
        #pragma unroll
        for (int t = 0; t < 2; t++) {
            int row = warp_m * 32 + t * 16 + lr;
            aoff[kc][t] = row * 128 + ((chunk ^ (row & 7)) << 4);
        }
        #pragma unroll
        for (int u = 0; u < 4; u++) {
            int row = warp_n * 64 + u * 16 + lr;
            boff[kc][u] = 16384 + row * 128 + ((chunk ^ (row & 7)) << 4);
        }
    }

    const int nch = K >> 6;
    stage_load(0, 0);
    stage_load(64, 1);

    for (int i = 0; i < nch; i++) {
        if (i < nch - 1) asm volatile("cp.async.wait_group 1;" ::: "memory");
        else             asm volatile("cp.async.wait_group 0;" ::: "memory");
        __syncthreads();
        if (i + 2 < nch) stage_load((i + 2) * 64, (i + 2) % 3);

        const uint32_t sb = sbase + (i % 3) * G_STAGE;
        #pragma unroll
        for (int kc = 0; kc < 4; kc++) {
            uint32_t ah[2][4], bh[4][4];
            #pragma unroll
            for (int t = 0; t < 2; t++) ldsm_x4(ah[t], sb + aoff[kc][t]);
            #pragma unroll
            for (int u = 0; u < 4; u++) ldsm_x4(bh[u], sb + boff[kc][u]);
            #pragma unroll
            for (int t = 0; t < 2; t++)
                #pragma unroll
                for (int u = 0; u < 4; u++) {
                    mma16816(acc[t][2 * u],     ah[t], bh[u][0], bh[u][2]);
                    mma16816(acc[t][2 * u + 1], ah[t], bh[u][1], bh[u][3]);
                }
        }
    }

    #pragma unroll
    for (int t = 0; t < 2; t++) {
        const int rbase = m0 + warp_m * 32 + t * 16 + (lane >> 2);
        #pragma unroll
        for (int j = 0; j < 8; j++) {
            const int col = n0 + warp_n * 64 + j * 8 + 2 * (lane & 3);
            const float b0 = __ldg(bias + col), b1 = __ldg(bias + col + 1);
            #pragma unroll
            for (int half = 0; half < 2; half++) {
                const int row = rbase + 8 * half;
                float v0 = acc[t][j][2 * half]     + b0;
                float v1 = acc[t][j][2 * half + 1] + b1;
                if (act) {
                    v0 = 0.5f * v0 * (1.0f + erff(v0 * 0.70710678118654752f));
                    v1 = 0.5f * v1 * (1.0f + erff(v1 * 0.70710678118654752f));
                }
                *(uint32_t*)(Oh + (size_t)row * N + col) = pack_h2(v0, v1);
            }
        }
    }
}

// ================= FA2-style attention (fp16, 64-query / 128-thread) =================
#define AT_BUF  16384
#define AT_SMEM (3 * AT_BUF)

__global__ __launch_bounds__(128) void attn_mma(
    const __half* __restrict__ Q, int ldq, int qoff,
    const __half* __restrict__ Kb, int ldk, int koff,
    const __half* __restrict__ Vb, int ldv, int voff,
    __half* __restrict__ Oh,
    const float* __restrict__ bias, float scale)
{
    extern __shared__ __align__(128) char smem[];
    const uint32_t sbase = smem_u32(smem);
    const int tid = threadIdx.x, lane = tid & 31, w = tid >> 5;
    const int qt = blockIdx.x, bh = blockIdx.y;
    const int b = bh & (BATCH - 1), h = bh >> 5;

    #pragma unroll
    for (int it = 0; it < 4; it++) {
        int idx = tid + it * 128, r = idx >> 3, c = idx & 7;
        uint32_t sw = r * 128 + ((c ^ (r & 7)) << 4);
        size_t g = (size_t)((qt * 64 + r) * BATCH + b) * ldq + qoff + h * HDIM + c * 8;
        cp_async16(sbase + sw, Q + g);
    }
    cp_commit();
    asm volatile("cp.async.wait_group 0;" ::: "memory");
    __syncthreads();

    const int lr = lane & 15, ls = lane >> 4;
    uint32_t qh[4][4];
    {
        int qrow = w * 16 + lr;
        #pragma unroll
        for (int kc = 0; kc < 4; kc++) {
            int chunk = 2 * kc + ls;
            uint32_t a = sbase + qrow * 128 + ((chunk ^ (qrow & 7)) << 4);
            ldsm_x4(qh[kc], a);
        }
    }
    __syncthreads();

    auto load_kt = [&](int kt, int st) {
        uint32_t sb = sbase + st * AT_BUF;
        #pragma unroll
        for (int it = 0; it < 4; it++) {
            int idx = tid + it * 128, r = idx >> 3, c = idx & 7;
            uint32_t sw = r * 128 + ((c ^ (r & 7)) << 4);
            size_t rowi = (size_t)((kt * 64 + r) * BATCH + b);
            cp_async16(sb + sw,        Kb + rowi * ldk + koff + h * HDIM + c * 8);
            cp_async16(sb + 8192 + sw, Vb + rowi * ldv + voff + h * HDIM + c * 8);
        }
        cp_commit();
    };
    load_kt(0, 0);
    load_kt(1, 1);

    float o[8][4];
    #pragma unroll
    for (int t = 0; t < 8; t++)
        #pragma unroll
        for (int e = 0; e < 4; e++) o[t][e] = 0.0f;
    float mrow0 = -1e30f, mrow1 = -1e30f, lsum0 = 0.0f, lsum1 = 0.0f;

    const int vkbase = ((lane & 16) ? 8 : 0) + (lane & 7);
    const int vcsel  = (lane >> 3) & 1;

    for (int kt = 0; kt < 8; kt++) {
        if (kt < 7) asm volatile("cp.async.wait_group 1;" ::: "memory");
        else        asm volatile("cp.async.wait_group 0;" ::: "memory");
        __syncthreads();
        if (kt + 2 < 8) load_kt(kt + 2, (kt + 2) % 3);
        const uint32_t sb = sbase + (kt % 3) * AT_BUF;

        float s[8][4];
        #pragma unroll
        for (int t = 0; t < 8; t++)
            #pragma unroll
            for (int e = 0; e < 4; e++) s[t][e] = 0.0f;
        #pragma unroll
        for (int kc = 0; kc < 4; kc++) {
            uint32_t kh[4][4];
            #pragma unroll
            for (int u = 0; u < 4; u++) {
                int krow = u * 16 + lr, chunk = 2 * kc + ls;
                uint32_t a = sb + krow * 128 + ((chunk ^ (krow & 7)) << 4);
                ldsm_x4(kh[u], a);
            }
            #pragma unroll
            for (int u = 0; u < 4; u++) {
                mma16816(s[2 * u],     qh[kc], kh[u][0], kh[u][2]);
                mma16816(s[2 * u + 1], qh[kc], kh[u][1], kh[u][3]);
            }
        }

        const int row0 = qt * 64 + w * 16 + (lane >> 2);
        if (bias) {
            #pragma unroll
            for (int t = 0; t < 8; t++) {
                int col = kt * 64 + t * 8 + 2 * (lane & 3);
                float2 b0 = *(const float2*)(bias + (size_t)row0 * TA + col);
                float2 b1 = *(const float2*)(bias + (size_t)(row0 + 8) * TA + col);
                s[t][0] = s[t][0] * scale + b0.x; s[t][1] = s[t][1] * scale + b0.y;
                s[t][2] = s[t][2] * scale + b1.x; s[t][3] = s[t][3] * scale + b1.y;
            }
        } else {
            #pragma unroll
            for (int t = 0; t < 8; t++)
                #pragma unroll
                for (int e = 0; e < 4; e++) s[t][e] *= scale;
        }

        float mx0 = -1e30f, mx1 = -1e30f;
        #pragma unroll
        for (int t = 0; t < 8; t++) {
            mx0 = fmaxf(mx0, fmaxf(s[t][0], s[t][1]));
            mx1 = fmaxf(mx1, fmaxf(s[t][2], s[t][3]));
        }
        mx0 = fmaxf(mx0, __shfl_xor_sync(0xffffffffu, mx0, 1));
        mx0 = fmaxf(mx0, __shfl_xor_sync(0xffffffffu, mx0, 2));
        mx1 = fmaxf(mx1, __shfl_xor_sync(0xffffffffu, mx1, 1));
        mx1 = fmaxf(mx1, __shfl_xor_sync(0xffffffffu, mx1, 2));
        float mn0 = fmaxf(mrow0, mx0), mn1 = fmaxf(mrow1, mx1);
        float a0 = __expf(mrow0 - mn0), a1 = __expf(mrow1 - mn1);
        mrow0 = mn0; mrow1 = mn1;

        float sum0 = 0.0f, sum1 = 0.0f;
        uint32_t phi[4][4];
        #pragma unroll
        for (int t = 0; t < 8; t++) {
            float p0 = __expf(s[t][0] - mn0), p1 = __expf(s[t][1] - mn0);
            float p2 = __expf(s[t][2] - mn1), p3 = __expf(s[t][3] - mn1);
            sum0 += p0 + p1; sum1 += p2 + p3;
            const int kc = t >> 1, j = (t & 1) * 2;
            phi[kc][j]     = pack_h2(p0, p1);
            phi[kc][j + 1] = pack_h2(p2, p3);
        }
        sum0 += __shfl_xor_sync(0xffffffffu, sum0, 1);
        sum0 += __shfl_xor_sync(0xffffffffu, sum0, 2);
        sum1 += __shfl_xor_sync(0xffffffffu, sum1, 1);
        sum1 += __shfl_xor_sync(0xffffffffu, sum1, 2);
        lsum0 = lsum0 * a0 + sum0;
        lsum1 = lsum1 * a1 + sum1;
        #pragma unroll
        for (int t = 0; t < 8; t++) {
            o[t][0] *= a0; o[t][1] *= a0;
            o[t][2] *= a1; o[t][3] *= a1;
        }

        #pragma unroll
        for (int kc = 0; kc < 4; kc++) {
            int vkey = kc * 16 + vkbase;
            uint32_t vh[4][4];
            #pragma unroll
            for (int du = 0; du < 4; du++) {
                int chunk = 2 * du + vcsel;
                uint32_t a = sb + 8192 + vkey * 128 + ((chunk ^ (vkey & 7)) << 4);
                ldsm_x4_t(vh[du], a);
            }
            #pragma unroll
            for (int du = 0; du < 4; du++) {
                mma16816(o[2 * du],     phi[kc], vh[du][0], vh[du][2]);
                mma16816(o[2 * du + 1], phi[kc], vh[du][1], vh[du][3]);
            }
        }
    }

    float inv0 = 1.0f / lsum0, inv1 = 1.0f / lsum1;
    const int row0 = qt * 64 + w * 16 + (lane >> 2);
    #pragma unroll
    for (int t = 0; t < 8; t++) {
        int col = t * 8 + 2 * (lane & 3);
        size_t off0 = (size_t)(row0 * BATCH + b) * D_MODEL + h * HDIM + col;
        size_t off1 = (size_t)((row0 + 8) * BATCH + b) * D_MODEL + h * HDIM + col;
        *(uint32_t*)(Oh + off0) = pack_h2(o[t][0] * inv0, o[t][1] * inv0);
        *(uint32_t*)(Oh + off1) = pack_h2(o[t][2] * inv1, o[t][3] * inv1);
    }
}

// ---------------- Bias precompute ----------------
__global__ void bias_kernel(const int* __restrict__ beats, float* __restrict__ out) {
    __shared__ int sb[NBEATS];
    int i = blockIdx.x;
    int j = threadIdx.x;
    if (threadIdx.x < NBEATS) sb[threadIdx.x] = beats[threadIdx.x];
    __syncthreads();
    float bb = 0.0f;
    #pragma unroll 8
    for (int n = 0; n < NBEATS; n++) {
        int bf = sb[n];
        if (j == bf) bb = fmaxf(bb, 2.0f);
        if (bf > 0      && j == bf - 1) bb = fmaxf(bb, 1.0f);
        if (bf < TA - 1 && j == bf + 1) bb = fmaxf(bb, 1.0f);
    }
    float scale = (float)(TA - 1) / (float)(TM - 1);
    float d = (float)i * scale - (float)j;
    out[i * TA + j] = -(d * d) * (1.0f / 32.0f) + bb;
}

// ---------------- Fused residual + LayerNorm ----------------
__global__ __launch_bounds__(256) void add_ln_kernel(
    const float* __restrict__ A, const __half* __restrict__ Bv,
    const float* __restrict__ gatePtr,
    const float* __restrict__ gamma, const float* __restrict__ beta,
    float* __restrict__ out, __half* __restrict__ oh)
{
    int t = blockIdx.x;
    int tid = threadIdx.x;
    float gscale = gatePtr ? tanhf(*gatePtr) : 1.0f;
    const float4* a4 = (const float4*)(A + (size_t)t * D_MODEL);
    const uint2*  b2 = (const uint2*)(Bv + (size_t)t * D_MODEL);
    float4 av = a4[tid];
    uint2 ub = b2[tid];
    __half2 h01 = *(__half2*)&ub.x;
    __half2 h23 = *(__half2*)&ub.y;
    float x0 = av.x + gscale * __low2float(h01);
    float x1 = av.y + gscale * __high2float(h01);
    float x2 = av.z + gscale * __low2float(h23);
    float x3 = av.w + gscale * __high2float(h23);
    float s  = x0 + x1 + x2 + x3;
    float ss = x0 * x0 + x1 * x1 + x2 * x2 + x3 * x3;

    __shared__ float rs[8], rss[8];
    #pragma unroll
    for (int o = 16; o > 0; o >>= 1) {
        s  += __shfl_xor_sync(0xffffffffu, s,  o);
        ss += __shfl_xor_sync(0xffffffffu, ss, o);
    }
    if ((tid & 31) == 0) { rs[tid >> 5] = s; rss[tid >> 5] = ss; }
    __syncthreads();
    float stot = 0.0f, sstot = 0.0f;
    #pragma unroll
    for (int i = 0; i < 8; i++) { stot += rs[i]; sstot += rss[i]; }
    float mean = stot * (1.0f / D_MODEL);
    float var  = sstot * (1.0f / D_MODEL) - mean * mean;
    float rstd = rsqrtf(var + LN_EPS);

    const float4* g4 = (const float4*)gamma;
    const float4* be4 = (const float4*)beta;
    float4 g = g4[tid], be = be4[tid];
    float4 o;
    o.x = (x0 - mean) * rstd * g.x + be.x;
    o.y = (x1 - mean) * rstd * g.y + be.y;
    o.z = (x2 - mean) * rstd * g.z + be.z;
    o.w = (x3 - mean) * rstd * g.w + be.w;
    ((float4*)(out + (size_t)t * D_MODEL))[tid] = o;
    if (oh) {
        uint2 uh;
        uh.x = pack_h2(o.x, o.y);
        uh.y = pack_h2(o.z, o.w);
        ((uint2*)(oh + (size_t)t * D_MODEL))[tid] = uh;
    }
}

// ---------------- Launch ----------------
extern "C" void kernel_launch(void* const* d_in, const int* in_sizes, int n_in,
                              void* d_out, int out_size) {
    const float* src      = (const float*)d_in[0];
    const float* audio    = (const float*)d_in[1];
    const int*   beats    = (const int*)  d_in[2];
    const float* sa_in_w  = (const float*)d_in[3];
    const float* sa_in_b  = (const float*)d_in[4];
    const float* sa_out_w = (const float*)d_in[5];
    const float* sa_out_b = (const float*)d_in[6];
    const float* ca_in_w  = (const float*)d_in[7];
    const float* ca_in_b  = (const float*)d_in[8];
    const float* ca_out_w = (const float*)d_in[9];
    const float* ca_out_b = (const float*)d_in[10];
    const float* gate     = (const float*)d_in[11];
    const float* n1_g     = (const float*)d_in[12];
    const float* n1_b     = (const float*)d_in[13];
    const float* nc_g     = (const float*)d_in[14];
    const float* nc_b     = (const float*)d_in[15];
    const float* n2_g     = (const float*)d_in[16];
    const float* n2_b     = (const float*)d_in[17];
    const float* lin1_w   = (const float*)d_in[18];
    const float* lin1_b   = (const float*)d_in[19];
    const float* lin2_w   = (const float*)d_in[20];
    const float* lin2_b   = (const float*)d_in[21];
    float* out = (float*)d_out;

    float *x1, *x2, *bias;
    __half *X, *AU, *TMP, *H, *W, *QKV, *KV, *CQ;
    cudaGetSymbolAddress((void**)&x1,   g_x1);
    cudaGetSymbolAddress((void**)&x2,   g_x2);
    cudaGetSymbolAddress((void**)&bias, g_bias);
    cudaGetSymbolAddress((void**)&X,    g_X);
    cudaGetSymbolAddress((void**)&AU,   g_AU);
    cudaGetSymbolAddress((void**)&TMP,  g_TMP);
    cudaGetSymbolAddress((void**)&H,    g_H);
    cudaGetSymbolAddress((void**)&W,    g_W);
    cudaGetSymbolAddress((void**)&QKV,  g_QKV);
    cudaGetSymbolAddress((void**)&KV,   g_KV);
    cudaGetSymbolAddress((void**)&CQ,   g_CQ);

    cudaFuncSetAttribute(gemm_mma, cudaFuncAttributeMaxDynamicSharedMemorySize, G_SMEM);
    cudaFuncSetAttribute(attn_mma, cudaFuncAttributeMaxDynamicSharedMemorySize, AT_SMEM);

    const int CVT_B = 256 * 4;
    #define H_NULL (__half*)nullptr
    #define GEMM1(a, bw, bp, oh, Nn, Kk, act) \
        gemm_mma<<<dim3((Nn) / 128, NTOK / 128), 256, G_SMEM>>>( \
            a, bw, bp, oh, Nn, Kk, act, H_NULL, H_NULL, nullptr, H_NULL, 0, 0)

    // 0-2) bias, weights, src+audio converts (fused)
    bias_kernel<<<TM, TA>>>(beats, bias);
    wcvt_kernel<<<W_TOTAL / CVT_B, 256>>>(sa_in_w, sa_out_w, ca_in_w, ca_out_w,
                                          lin1_w, lin2_w, W);
    {
        const int nb = NTOK * D_MODEL / CVT_B;
        cvt2_kernel<<<2 * nb, 256>>>(src, X, audio, AU, nb);
    }

    // 3) fused: SA packed QKV (24 tiles) + CA KV-proj (16 tiles)
    gemm_mma<<<dim3(40, NTOK / 128), 256, G_SMEM>>>(
        X, W + W_SAIN, sa_in_b, QKV, 3 * D_MODEL, D_MODEL, 0,
        AU, W + W_CAIN + (size_t)D_MODEL * D_MODEL, ca_in_b + D_MODEL,
        KV, 2 * D_MODEL, 24);

    // 4) SA attention (64-query / 128-thread blocks)
    attn_mma<<<dim3(TM / 64, BATCH * NHEAD), 128, AT_SMEM>>>(
        QKV, 3 * D_MODEL, 0,
        QKV, 3 * D_MODEL, D_MODEL,
        QKV, 3 * D_MODEL, 2 * D_MODEL,
        X, nullptr, 0.125f);

    // 5) SA out-proj (fp16 out)
    GEMM1(X, W + W_SAOUT, sa_out_b, TMP, D_MODEL, D_MODEL, 0);

    // 6) x1 = LN1(src + sa), fused fp16 out
    add_ln_kernel<<<NTOK, 256>>>(src, TMP, nullptr, n1_g, n1_b, x1, X);

    // 7) CA Q-proj
    GEMM1(X, W + W_CAIN, ca_in_b, CQ, D_MODEL, D_MODEL, 0);

    // 8) CA attention (biased)
    attn_mma<<<dim3(TM / 64, BATCH * NHEAD), 128, AT_SMEM>>>(
        CQ, D_MODEL, 0,
        KV, 2 * D_MODEL, 0,
        KV, 2 * D_MODEL, D_MODEL,
        X, bias, 0.125f);

    // 9) CA out-proj (fp16 out)
    GEMM1(X, W + W_CAOUT, ca_out_b, TMP, D_MODEL, D_MODEL, 0);

    // 10) x2 = LNc(x1 + tanh(gate)*cross), fused fp16 out
    add_ln_kernel<<<NTOK, 256>>>(x1, TMP, gate, nc_g, nc_b, x2, X);

    // 11-12) FFN
    GEMM1(X, W + W_LIN1, lin1_b, H, DFF, D_MODEL, 1);
    GEMM1(H, W + W_LIN2, lin2_b, TMP, D_MODEL, DFF, 0);

    // 13) out = LN2(x2 + ff)
    add_ln_kernel<<<NTOK, 256>>>(x2, TMP, nullptr, n2_g, n2_b, out, H_NULL);
}

// round 16
// speedup vs baseline: 1.0130x; 1.0088x over previous
#include <cuda_runtime.h>
#include <cuda_fp16.h>
#include <math.h>
#include <stdint.h>

// ---------------- Problem constants ----------------
#define D_MODEL 1024
#define NHEAD   16
#define HDIM    64
#define DFF     4096
#define TM      512
#define TA      512
#define BATCH   32
#define NTOK    (TM * BATCH)   // 16384
#define NBEATS  64
#define LN_EPS  1e-5f

// ---------------- fp32 scratch ----------------
__device__ float g_x1  [NTOK * D_MODEL];
__device__ float g_x2  [NTOK * D_MODEL];
__device__ float g_bias[TM * TA];

// ---------------- fp16 scratch ----------------
__device__ __half g_X  [NTOK * D_MODEL];
__device__ __half g_AU [NTOK * D_MODEL];
__device__ __half g_TMP[NTOK * D_MODEL];
__device__ __half g_H  [NTOK * DFF];
__device__ __half g_QKV[NTOK * 3 * D_MODEL];
__device__ __half g_KV [NTOK * 2 * D_MODEL];
__device__ __half g_CQ [NTOK * D_MODEL];
__device__ __half g_W  [16777216];

#define W_SAIN   0
#define W_SAOUT  3145728
#define W_CAIN   4194304
#define W_CAOUT  7340032
#define W_LIN1   8388608
#define W_LIN2  12582912
#define W_TOTAL 16777216

// ================= helpers (non-'a' PTX only) =================
__device__ __forceinline__ uint32_t smem_u32(const void* p) {
    uint32_t a;
    asm("{ .reg .u64 t; cvta.to.shared.u64 t, %1; cvt.u32.u64 %0, t; }" : "=r"(a) : "l"(p));
    return a;
}
__device__ __forceinline__ void cp_async16(uint32_t saddr, const void* g) {
    asm volatile("cp.async.cg.shared.global [%0], [%1], 16;" :: "r"(saddr), "l"(g));
}
__device__ __forceinline__ void cp_commit() {
    asm volatile("cp.async.commit_group;" ::: "memory");
}
__device__ __forceinline__ void ldsm_x4(uint32_t (&r)[4], uint32_t addr) {
    asm volatile("ldmatrix.sync.aligned.m8n8.x4.shared.b16 {%0,%1,%2,%3}, [%4];"
                 : "=r"(r[0]), "=r"(r[1]), "=r"(r[2]), "=r"(r[3]) : "r"(addr));
}
__device__ __forceinline__ void ldsm_x4_t(uint32_t (&r)[4], uint32_t addr) {
    asm volatile("ldmatrix.sync.aligned.m8n8.x4.trans.shared.b16 {%0,%1,%2,%3}, [%4];"
                 : "=r"(r[0]), "=r"(r[1]), "=r"(r[2]), "=r"(r[3]) : "r"(addr));
}
__device__ __forceinline__ void mma16816(float (&d)[4], const uint32_t (&a)[4],
                                         uint32_t b0, uint32_t b1) {
    asm volatile(
        "mma.sync.aligned.m16n8k16.row.col.f32.f16.f16.f32 "
        "{%0,%1,%2,%3}, {%4,%5,%6,%7}, {%8,%9}, {%0,%1,%2,%3};"
        : "+f"(d[0]), "+f"(d[1]), "+f"(d[2]), "+f"(d[3])
        : "r"(a[0]), "r"(a[1]), "r"(a[2]), "r"(a[3]), "r"(b0), "r"(b1));
}
__device__ __forceinline__ uint32_t pack_h2(float x, float y) {
    return (uint32_t)__half_as_ushort(__float2half_rn(x)) |
           ((uint32_t)__half_as_ushort(__float2half_rn(y)) << 16);
}

// ================= converts =================
__global__ __launch_bounds__(256) void cvt2_kernel(
    const float* __restrict__ s0, __half* __restrict__ d0,
    const float* __restrict__ s1, __half* __restrict__ d1, int nb)
{
    const float* s = s0; __half* d = d0;
    int bx = blockIdx.x;
    if (bx >= nb) { s = s1; d = d1; bx -= nb; }
    int i = (bx * 256 + threadIdx.x) * 4;
    float4 v = *(const float4*)(s + i);
    uint2 uh;
    uh.x = pack_h2(v.x, v.y);
    uh.y = pack_h2(v.z, v.w);
    *(uint2*)(d + i) = uh;
}

__global__ __launch_bounds__(256) void wcvt_kernel(
    const float* __restrict__ w0, const float* __restrict__ w1,
    const float* __restrict__ w2, const float* __restrict__ w3,
    const float* __restrict__ w4, const float* __restrict__ w5,
    __half* __restrict__ hi)
{
    int i = (blockIdx.x * 256 + threadIdx.x) * 4;
    const float* src; int off;
    if      (i < W_SAOUT) { src = w0; off = W_SAIN; }
    else if (i < W_CAIN)  { src = w1; off = W_SAOUT; }
    else if (i < W_CAOUT) { src = w2; off = W_CAIN; }
    else if (i < W_LIN1)  { src = w3; off = W_CAOUT; }
    else if (i < W_LIN2)  { src = w4; off = W_LIN1; }
    else                  { src = w5; off = W_LIN2; }
    float4 v = *(const float4*)(src + (i - off));
    uint2 uh;
    uh.x = pack_h2(v.x, v.y);
    uh.y = pack_h2(v.z, v.w);
    *(uint2*)(hi + i) = uh;
}

// ================= mma.sync GEMM (fp16, BK=64, double-buffered fragments) =================
#define G_STAGE 32768
#define G_SMEM  (3 * G_STAGE)

__global__ __launch_bounds__(256, 2) void gemm_mma(
    const __half* __restrict__ A, const __half* __restrict__ B,
    const float* __restrict__ bias, __half* __restrict__ Oh,
    int N, int K, int act,
    const __half* A2, const __half* B2, const float* bias2,
    __half* Oh2, int N2, int nx1)
{
    extern __shared__ __align__(128) char smem[];
    const uint32_t sbase = smem_u32(smem);
    const int tid = threadIdx.x;
    const int lane = tid & 31, wid = tid >> 5;
    const int warp_m = wid & 3, warp_n = wid >> 2;

    int bx = blockIdx.x;
    if (A2 && bx >= nx1) {
        A = A2; B = B2; bias = bias2; Oh = Oh2; N = N2;
        bx -= nx1;
    }
    const int m0 = blockIdx.y * 128, n0 = bx * 128;

    float acc[2][8][4];
    #pragma unroll
    for (int t = 0; t < 2; t++)
        #pragma unroll
        for (int j = 0; j < 8; j++)
            #pragma unroll
            for (int e = 0; e < 4; e++) acc[t][j][e] = 0.0f;

    // ---- hoisted load addressing
    const int lrr = tid >> 3, lcc = tid & 7;
    uint32_t lsw[4];
    const __half* gA[4];
    const __half* gB[4];
    #pragma unroll
    for (int it = 0; it < 4; it++) {
        int r = lrr + it * 32;
        lsw[it] = r * 128 + ((lcc ^ (r & 7)) << 4);
        gA[it] = A + (size_t)(m0 + r) * K + lcc * 8;
        gB[it] = B + (size_t)(n0 + r) * K + lcc * 8;
    }

    auto stage_load = [&](int kk, int st) {
        const uint32_t sb = sbase + st * G_STAGE;
        #pragma unroll
        for (int it = 0; it < 4; it++)
            cp_async16(sb + lsw[it], gA[it] + kk);
        #pragma unroll
        for (int it = 0; it < 4; it++)
            cp_async16(sb + 16384 + lsw[it], gB[it] + kk);
        cp_commit();
    };

    const int lr = lane & 15;
    const int lseg = lane >> 4;
    uint32_t aoff[4][2], boff[4][4];
    #pragma unroll
    for (int kc = 0; kc < 4; kc++) {
        const int chunk = 2 * kc + lseg;
        #pragma unroll
        for (int t = 0; t < 2; t++) {
            int row = warp_m * 32 + t * 16 + lr;
            aoff[kc][t] = row * 128 + ((chunk ^ (row & 7)) << 4);
        }
        #pragma unroll
        for (int u = 0; u < 4; u++) {
            int row = warp_n * 64 + u * 16 + lr;
            boff[kc][u] = 16384 + row * 128 + ((chunk ^ (row & 7)) << 4);
        }
    }

    const int nch = K >> 6;
    stage_load(0, 0);
    stage_load(64, 1);

    for (int i = 0; i < nch; i++) {
        if (i < nch - 1) asm volatile("cp.async.wait_group 1;" ::: "memory");
        else             asm volatile("cp.async.wait_group 0;" ::: "memory");
        __syncthreads();
        if (i + 2 < nch) stage_load((i + 2) * 64, (i + 2) % 3);

        const uint32_t sb = sbase + (i % 3) * G_STAGE;
        // double-buffered fragments: ldsm for kc+1 overlaps MMAs of kc
        uint32_t ah[2][2][4], bh[2][4][4];
        #pragma unroll
        for (int t = 0; t < 2; t++) ldsm_x4(ah[0][t], sb + aoff[0][t]);
        #pragma unroll
        for (int u = 0; u < 4; u++) ldsm_x4(bh[0][u], sb + boff[0][u]);

        #pragma unroll
        for (int kc = 0; kc < 4; kc++) {
            const int cur = kc & 1, nxt = cur ^ 1;
            if (kc < 3) {
                #pragma unroll
                for (int t = 0; t < 2; t++) ldsm_x4(ah[nxt][t], sb + aoff[kc + 1][t]);
                #pragma unroll
                for (int u = 0; u < 4; u++) ldsm_x4(bh[nxt][u], sb + boff[kc + 1][u]);
            }
            #pragma unroll
            for (int t = 0; t < 2; t++)
                #pragma unroll
                for (int u = 0; u < 4; u++) {
                    mma16816(acc[t][2 * u],     ah[cur][t], bh[cur][u][0], bh[cur][u][2]);
                    mma16816(acc[t][2 * u + 1], ah[cur][t], bh[cur][u][1], bh[cur][u][3]);
                }
        }
    }

    #pragma unroll
    for (int t = 0; t < 2; t++) {
        const int rbase = m0 + warp_m * 32 + t * 16 + (lane >> 2);
        #pragma unroll
        for (int j = 0; j < 8; j++) {
            const int col = n0 + warp_n * 64 + j * 8 + 2 * (lane & 3);
            const float b0 = __ldg(bias + col), b1 = __ldg(bias + col + 1);
            #pragma unroll
            for (int half = 0; half < 2; half++) {
                const int row = rbase + 8 * half;
                float v0 = acc[t][j][2 * half]     + b0;
                float v1 = acc[t][j][2 * half + 1] + b1;
                if (act) {
                    v0 = 0.5f * v0 * (1.0f + erff(v0 * 0.70710678118654752f));
                    v1 = 0.5f * v1 * (1.0f + erff(v1 * 0.70710678118654752f));
                }
                *(uint32_t*)(Oh + (size_t)row * N + col) = pack_h2(v0, v1);
            }
        }
    }
}

// ================= FA2-style attention (fp16, 64-query / 128-thread) =================
#define AT_BUF  16384
#define AT_SMEM (3 * AT_BUF)

__global__ __launch_bounds__(128) void attn_mma(
    const __half* __restrict__ Q, int ldq, int qoff,
    const __half* __restrict__ Kb, int ldk, int koff,
    const __half* __restrict__ Vb, int ldv, int voff,
    __half* __restrict__ Oh,
    const float* __restrict__ bias, float scale)
{
    extern __shared__ __align__(128) char smem[];
    const uint32_t sbase = smem_u32(smem);
    const int tid = threadIdx.x, lane = tid & 31, w = tid >> 5;
    const int qt = blockIdx.x, bh = blockIdx.y;
    const int b = bh & (BATCH - 1), h = bh >> 5;

    #pragma unroll
    for (int it = 0; it < 4; it++) {
        int idx = tid + it * 128, r = idx >> 3, c = idx & 7;
        uint32_t sw = r * 128 + ((c ^ (r & 7)) << 4);
        size_t g = (size_t)((qt * 64 + r) * BATCH + b) * ldq + qoff + h * HDIM + c * 8;
        cp_async16(sbase + sw, Q + g);
    }
    cp_commit();
    asm volatile("cp.async.wait_group 0;" ::: "memory");
    __syncthreads();

    const int lr = lane & 15, ls = lane >> 4;
    uint32_t qh[4][4];
    {
        int qrow = w * 16 + lr;
        #pragma unroll
        for (int kc = 0; kc < 4; kc++) {
            int chunk = 2 * kc + ls;
            uint32_t a = sbase + qrow * 128 + ((chunk ^ (qrow & 7)) << 4);
            ldsm_x4(qh[kc], a);
        }
    }
    __syncthreads();

    auto load_kt = [&](int kt, int st) {
        uint32_t sb = sbase + st * AT_BUF;
        #pragma unroll
        for (int it = 0; it < 4; it++) {
            int idx = tid + it * 128, r = idx >> 3, c = idx & 7;
            uint32_t sw = r * 128 + ((c ^ (r & 7)) << 4);
            size_t rowi = (size_t)((kt * 64 + r) * BATCH + b);
            cp_async16(sb + sw,        Kb + rowi * ldk + koff + h * HDIM + c * 8);
            cp_async16(sb + 8192 + sw, Vb + rowi * ldv + voff + h * HDIM + c * 8);
        }
        cp_commit();
    };
    load_kt(0, 0);
    load_kt(1, 1);

    float o[8][4];
    #pragma unroll
    for (int t = 0; t < 8; t++)
        #pragma unroll
        for (int e = 0; e < 4; e++) o[t][e] = 0.0f;
    float mrow0 = -1e30f, mrow1 = -1e30f, lsum0 = 0.0f, lsum1 = 0.0f;

    const int vkbase = ((lane & 16) ? 8 : 0) + (lane & 7);
    const int vcsel  = (lane >> 3) & 1;

    for (int kt = 0; kt < 8; kt++) {
        if (kt < 7) asm volatile("cp.async.wait_group 1;" ::: "memory");
        else        asm volatile("cp.async.wait_group 0;" ::: "memory");
        __syncthreads();
        if (kt + 2 < 8) load_kt(kt + 2, (kt + 2) % 3);
        const uint32_t sb = sbase + (kt % 3) * AT_BUF;

        float s[8][4];
        #pragma unroll
        for (int t = 0; t < 8; t++)
            #pragma unroll
            for (int e = 0; e < 4; e++) s[t][e] = 0.0f;
        #pragma unroll
        for (int kc = 0; kc < 4; kc++) {
            uint32_t kh[4][4];
            #pragma unroll
            for (int u = 0; u < 4; u++) {
                int krow = u * 16 + lr, chunk = 2 * kc + ls;
                uint32_t a = sb + krow * 128 + ((chunk ^ (krow & 7)) << 4);
                ldsm_x4(kh[u], a);
            }
            #pragma unroll
            for (int u = 0; u < 4; u++) {
                mma16816(s[2 * u],     qh[kc], kh[u][0], kh[u][2]);
                mma16816(s[2 * u + 1], qh[kc], kh[u][1], kh[u][3]);
            }
        }

        const int row0 = qt * 64 + w * 16 + (lane >> 2);
        if (bias) {
            #pragma unroll
            for (int t = 0; t < 8; t++) {
                int col = kt * 64 + t * 8 + 2 * (lane & 3);
                float2 b0 = *(const float2*)(bias + (size_t)row0 * TA + col);
                float2 b1 = *(const float2*)(bias + (size_t)(row0 + 8) * TA + col);
                s[t][0] = s[t][0] * scale + b0.x; s[t][1] = s[t][1] * scale + b0.y;
                s[t][2] = s[t][2] * scale + b1.x; s[t][3] = s[t][3] * scale + b1.y;
            }
        } else {
            #pragma unroll
            for (int t = 0; t < 8; t++)
                #pragma unroll
                for (int e = 0; e < 4; e++) s[t][e] *= scale;
        }

        float mx0 = -1e30f, mx1 = -1e30f;
        #pragma unroll
        for (int t = 0; t < 8; t++) {
            mx0 = fmaxf(mx0, fmaxf(s[t][0], s[t][1]));
            mx1 = fmaxf(mx1, fmaxf(s[t][2], s[t][3]));
        }
        mx0 = fmaxf(mx0, __shfl_xor_sync(0xffffffffu, mx0, 1));
        mx0 = fmaxf(mx0, __shfl_xor_sync(0xffffffffu, mx0, 2));
        mx1 = fmaxf(mx1, __shfl_xor_sync(0xffffffffu, mx1, 1));
        mx1 = fmaxf(mx1, __shfl_xor_sync(0xffffffffu, mx1, 2));
        float mn0 = fmaxf(mrow0, mx0), mn1 = fmaxf(mrow1, mx1);
        float a0 = __expf(mrow0 - mn0), a1 = __expf(mrow1 - mn1);
        mrow0 = mn0; mrow1 = mn1;

        float sum0 = 0.0f, sum1 = 0.0f;
        uint32_t phi[4][4];
        #pragma unroll
        for (int t = 0; t < 8; t++) {
            float p0 = __expf(s[t][0] - mn0), p1 = __expf(s[t][1] - mn0);
            float p2 = __expf(s[t][2] - mn1), p3 = __expf(s[t][3] - mn1);
            sum0 += p0 + p1; sum1 += p2 + p3;
            const int kc = t >> 1, j = (t & 1) * 2;
            phi[kc][j]     = pack_h2(p0, p1);
            phi[kc][j + 1] = pack_h2(p2, p3);
        }
        sum0 += __shfl_xor_sync(0xffffffffu, sum0, 1);
        sum0 += __shfl_xor_sync(0xffffffffu, sum0, 2);
        sum1 += __shfl_xor_sync(0xffffffffu, sum1, 1);
        sum1 += __shfl_xor_sync(0xffffffffu, sum1, 2);
        lsum0 = lsum0 * a0 + sum0;
        lsum1 = lsum1 * a1 + sum1;
        #pragma unroll
        for (int t = 0; t < 8; t++) {
            o[t][0] *= a0; o[t][1] *= a0;
            o[t][2] *= a1; o[t][3] *= a1;
        }

        #pragma unroll
        for (int kc = 0; kc < 4; kc++) {
            int vkey = kc * 16 + vkbase;
            uint32_t vh[4][4];
            #pragma unroll
            for (int du = 0; du < 4; du++) {
                int chunk = 2 * du + vcsel;
                uint32_t a = sb + 8192 + vkey * 128 + ((chunk ^ (vkey & 7)) << 4);
                ldsm_x4_t(vh[du], a);
            }
            #pragma unroll
            for (int du = 0; du < 4; du++) {
                mma16816(o[2 * du],     phi[kc], vh[du][0], vh[du][2]);
                mma16816(o[2 * du + 1], phi[kc], vh[du][1], vh[du][3]);
            }
        }
    }

    float inv0 = 1.0f / lsum0, inv1 = 1.0f / lsum1;
    const int row0 = qt * 64 + w * 16 + (lane >> 2);
    #pragma unroll
    for (int t = 0; t < 8; t++) {
        int col = t * 8 + 2 * (lane & 3);
        size_t off0 = (size_t)(row0 * BATCH + b) * D_MODEL + h * HDIM + col;
        size_t off1 = (size_t)((row0 + 8) * BATCH + b) * D_MODEL + h * HDIM + col;
        *(uint32_t*)(Oh + off0) = pack_h2(o[t][0] * inv0, o[t][1] * inv0);
        *(uint32_t*)(Oh + off1) = pack_h2(o[t][2] * inv1, o[t][3] * inv1);
    }
}

// ---------------- Bias precompute ----------------
__global__ void bias_kernel(const int* __restrict__ beats, float* __restrict__ out) {
    __shared__ int sb[NBEATS];
    int i = blockIdx.x;
    int j = threadIdx.x;
    if (threadIdx.x < NBEATS) sb[threadIdx.x] = beats[threadIdx.x];
    __syncthreads();
    float bb = 0.0f;
    #pragma unroll 8
    for (int n = 0; n < NBEATS; n++) {
        int bf = sb[n];
        if (j == bf) bb = fmaxf(bb, 2.0f);
        if (bf > 0      && j == bf - 1) bb = fmaxf(bb, 1.0f);
        if (bf < TA - 1 && j == bf + 1) bb = fmaxf(bb, 1.0f);
    }
    float scale = (float)(TA - 1) / (float)(TM - 1);
    float d = (float)i * scale - (float)j;
    out[i * TA + j] = -(d * d) * (1.0f / 32.0f) + bb;
}

// ---------------- Fused residual + LayerNorm ----------------
__global__ __launch_bounds__(256) void add_ln_kernel(
    const float* __restrict__ A, const __half* __restrict__ Bv,
    const float* __restrict__ gatePtr,
    const float* __restrict__ gamma, const float* __restrict__ beta,
    float* __restrict__ out, __half* __restrict__ oh)
{
    int t = blockIdx.x;
    int tid = threadIdx.x;
    float gscale = gatePtr ? tanhf(*gatePtr) : 1.0f;
    const float4* a4 = (const float4*)(A + (size_t)t * D_MODEL);
    const uint2*  b2 = (const uint2*)(Bv + (size_t)t * D_MODEL);
    float4 av = a4[tid];
    uint2 ub = b2[tid];
    __half2 h01 = *(__half2*)&ub.x;
    __half2 h23 = *(__half2*)&ub.y;
    float x0 = av.x + gscale * __low2float(h01);
    float x1 = av.y + gscale * __high2float(h01);
    float x2 = av.z + gscale * __low2float(h23);
    float x3 = av.w + gscale * __high2float(h23);
    float s  = x0 + x1 + x2 + x3;
    float ss = x0 * x0 + x1 * x1 + x2 * x2 + x3 * x3;

    __shared__ float rs[8], rss[8];
    #pragma unroll
    for (int o = 16; o > 0; o >>= 1) {
        s  += __shfl_xor_sync(0xffffffffu, s,  o);
        ss += __shfl_xor_sync(0xffffffffu, ss, o);
    }
    if ((tid & 31) == 0) { rs[tid >> 5] = s; rss[tid >> 5] = ss; }
    __syncthreads();
    float stot = 0.0f, sstot = 0.0f;
    #pragma unroll
    for (int i = 0; i < 8; i++) { stot += rs[i]; sstot += rss[i]; }
    float mean = stot * (1.0f / D_MODEL);
    float var  = sstot * (1.0f / D_MODEL) - mean * mean;
    float rstd = rsqrtf(var + LN_EPS);

    const float4* g4 = (const float4*)gamma;
    const float4* be4 = (const float4*)beta;
    float4 g = g4[tid], be = be4[tid];
    float4 o;
    o.x = (x0 - mean) * rstd * g.x + be.x;
    o.y = (x1 - mean) * rstd * g.y + be.y;
    o.z = (x2 - mean) * rstd * g.z + be.z;
    o.w = (x3 - mean) * rstd * g.w + be.w;
    ((float4*)(out + (size_t)t * D_MODEL))[tid] = o;
    if (oh) {
        uint2 uh;
        uh.x = pack_h2(o.x, o.y);
        uh.y = pack_h2(o.z, o.w);
        ((uint2*)(oh + (size_t)t * D_MODEL))[tid] = uh;
    }
}

// ---------------- Launch ----------------
extern "C" void kernel_launch(void* const* d_in, const int* in_sizes, int n_in,
                              void* d_out, int out_size) {
    const float* src      = (const float*)d_in[0];
    const float* audio    = (const float*)d_in[1];
    const int*   beats    = (const int*)  d_in[2];
    const float* sa_in_w  = (const float*)d_in[3];
    const float* sa_in_b  = (const float*)d_in[4];
    const float* sa_out_w = (const float*)d_in[5];
    const float* sa_out_b = (const float*)d_in[6];
    const float* ca_in_w  = (const float*)d_in[7];
    const float* ca_in_b  = (const float*)d_in[8];
    const float* ca_out_w = (const float*)d_in[9];
    const float* ca_out_b = (const float*)d_in[10];
    const float* gate     = (const float*)d_in[11];
    const float* n1_g     = (const float*)d_in[12];
    const float* n1_b     = (const float*)d_in[13];
    const float* nc_g     = (const float*)d_in[14];
    const float* nc_b     = (const float*)d_in[15];
    const float* n2_g     = (const float*)d_in[16];
    const float* n2_b     = (const float*)d_in[17];
    const float* lin1_w   = (const float*)d_in[18];
    const float* lin1_b   = (const float*)d_in[19];
    const float* lin2_w   = (const float*)d_in[20];
    const float* lin2_b   = (const float*)d_in[21];
    float* out = (float*)d_out;

    float *x1, *x2, *bias;
    __half *X, *AU, *TMP, *H, *W, *QKV, *KV, *CQ;
    cudaGetSymbolAddress((void**)&x1,   g_x1);
    cudaGetSymbolAddress((void**)&x2,   g_x2);
    cudaGetSymbolAddress((void**)&bias, g_bias);
    cudaGetSymbolAddress((void**)&X,    g_X);
    cudaGetSymbolAddress((void**)&AU,   g_AU);
    cudaGetSymbolAddress((void**)&TMP,  g_TMP);
    cudaGetSymbolAddress((void**)&H,    g_H);
    cudaGetSymbolAddress((void**)&W,    g_W);
    cudaGetSymbolAddress((void**)&QKV,  g_QKV);
    cudaGetSymbolAddress((void**)&KV,   g_KV);
    cudaGetSymbolAddress((void**)&CQ,   g_CQ);

    cudaFuncSetAttribute(gemm_mma, cudaFuncAttributeMaxDynamicSharedMemorySize, G_SMEM);
    cudaFuncSetAttribute(attn_mma, cudaFuncAttributeMaxDynamicSharedMemorySize, AT_SMEM);

    const int CVT_B = 256 * 4;
    #define H_NULL (__half*)nullptr
    #define GEMM1(a, bw, bp, oh, Nn, Kk, act) \
        gemm_mma<<<dim3((Nn) / 128, NTOK / 128), 256, G_SMEM>>>( \
            a, bw, bp, oh, Nn, Kk, act, H_NULL, H_NULL, nullptr, H_NULL, 0, 0)

    // 0-2) bias, weights, src+audio converts (fused)
    bias_kernel<<<TM, TA>>>(beats, bias);
    wcvt_kernel<<<W_TOTAL / CVT_B, 256>>>(sa_in_w, sa_out_w, ca_in_w, ca_out_w,
                                          lin1_w, lin2_w, W);
    {
        const int nb = NTOK * D_MODEL / CVT_B;
        cvt2_kernel<<<2 * nb, 256>>>(src, X, audio, AU, nb);
    }

    // 3) fused: SA packed QKV (24 tiles) + CA KV-proj (16 tiles)
    gemm_mma<<<dim3(40, NTOK / 128), 256, G_SMEM>>>(
        X, W + W_SAIN, sa_in_b, QKV, 3 * D_MODEL, D_MODEL, 0,
        AU, W + W_CAIN + (size_t)D_MODEL * D_MODEL, ca_in_b + D_MODEL,
        KV, 2 * D_MODEL, 24);

    // 4) SA attention (64-query / 128-thread blocks)
    attn_mma<<<dim3(TM / 64, BATCH * NHEAD), 128, AT_SMEM>>>(
        QKV, 3 * D_MODEL, 0,
        QKV, 3 * D_MODEL, D_MODEL,
        QKV, 3 * D_MODEL, 2 * D_MODEL,
        X, nullptr, 0.125f);

    // 5) SA out-proj (fp16 out)
    GEMM1(X, W + W_SAOUT, sa_out_b, TMP, D_MODEL, D_MODEL, 0);

    // 6) x1 = LN1(src + sa), fused fp16 out
    add_ln_kernel<<<NTOK, 256>>>(src, TMP, nullptr, n1_g, n1_b, x1, X);

    // 7) CA Q-proj
    GEMM1(X, W + W_CAIN, ca_in_b, CQ, D_MODEL, D_MODEL, 0);

    // 8) CA attention (biased)
    attn_mma<<<dim3(TM / 64, BATCH * NHEAD), 128, AT_SMEM>>>(
        CQ, D_MODEL, 0,
        KV, 2 * D_MODEL, 0,
        KV, 2 * D_MODEL, D_MODEL,
        X, bias, 0.125f);

    // 9) CA out-proj (fp16 out)
    GEMM1(X, W + W_CAOUT, ca_out_b, TMP, D_MODEL, D_MODEL, 0);

    // 10) x2 = LNc(x1 + tanh(gate)*cross), fused fp16 out
    add_ln_kernel<<<NTOK, 256>>>(x1, TMP, gate, nc_g, nc_b, x2, X);

    // 11-12) FFN
    GEMM1(X, W + W_LIN1, lin1_b, H, DFF, D_MODEL, 1);
    GEMM1(H, W + W_LIN2, lin2_b, TMP, D_MODEL, DFF, 0);

    // 13) out = LN2(x2 + ff)
    add_ln_kernel<<<NTOK, 256>>>(x2, TMP, nullptr, n2_g, n2_b, out, H_NULL);
}

// round 17
// speedup vs baseline: 1.0171x; 1.0041x over previous
#include <cuda_runtime.h>
#include <cuda_fp16.h>
#include <math.h>
#include <stdint.h>

// ---------------- Problem constants ----------------
#define D_MODEL 1024
#define NHEAD   16
#define HDIM    64
#define DFF     4096
#define TM      512
#define TA      512
#define BATCH   32
#define NTOK    (TM * BATCH)   // 16384
#define NBEATS  64
#define LN_EPS  1e-5f

// ---------------- scratch ----------------
__device__ float  g_bias[TM * TA];
__device__ __half g_X  [NTOK * D_MODEL];
__device__ __half g_AU [NTOK * D_MODEL];
__device__ __half g_TMP[NTOK * D_MODEL];
__device__ __half g_X1H[NTOK * D_MODEL];
__device__ __half g_X2H[NTOK * D_MODEL];
__device__ __half g_H  [NTOK * DFF];
__device__ __half g_QKV[NTOK * 3 * D_MODEL];
__device__ __half g_KV [NTOK * 2 * D_MODEL];
__device__ __half g_CQ [NTOK * D_MODEL];
__device__ __half g_W  [16777216];

#define W_SAIN   0
#define W_SAOUT  3145728
#define W_CAIN   4194304
#define W_CAOUT  7340032
#define W_LIN1   8388608
#define W_LIN2  12582912
#define W_TOTAL 16777216

// ================= helpers (non-'a' PTX only) =================
__device__ __forceinline__ uint32_t smem_u32(const void* p) {
    uint32_t a;
    asm("{ .reg .u64 t; cvta.to.shared.u64 t, %1; cvt.u32.u64 %0, t; }" : "=r"(a) : "l"(p));
    return a;
}
__device__ __forceinline__ void cp_async16(uint32_t saddr, const void* g) {
    asm volatile("cp.async.cg.shared.global [%0], [%1], 16;" :: "r"(saddr), "l"(g));
}
__device__ __forceinline__ void cp_commit() {
    asm volatile("cp.async.commit_group;" ::: "memory");
}
__device__ __forceinline__ void ldsm_x4(uint32_t (&r)[4], uint32_t addr) {
    asm volatile("ldmatrix.sync.aligned.m8n8.x4.shared.b16 {%0,%1,%2,%3}, [%4];"
                 : "=r"(r[0]), "=r"(r[1]), "=r"(r[2]), "=r"(r[3]) : "r"(addr));
}
__device__ __forceinline__ void ldsm_x4_t(uint32_t (&r)[4], uint32_t addr) {
    asm volatile("ldmatrix.sync.aligned.m8n8.x4.trans.shared.b16 {%0,%1,%2,%3}, [%4];"
                 : "=r"(r[0]), "=r"(r[1]), "=r"(r[2]), "=r"(r[3]) : "r"(addr));
}
__device__ __forceinline__ void mma16816(float (&d)[4], const uint32_t (&a)[4],
                                         uint32_t b0, uint32_t b1) {
    asm volatile(
        "mma.sync.aligned.m16n8k16.row.col.f32.f16.f16.f32 "
        "{%0,%1,%2,%3}, {%4,%5,%6,%7}, {%8,%9}, {%0,%1,%2,%3};"
        : "+f"(d[0]), "+f"(d[1]), "+f"(d[2]), "+f"(d[3])
        : "r"(a[0]), "r"(a[1]), "r"(a[2]), "r"(a[3]), "r"(b0), "r"(b1));
}
__device__ __forceinline__ uint32_t pack_h2(float x, float y) {
    return (uint32_t)__half_as_ushort(__float2half_rn(x)) |
           ((uint32_t)__half_as_ushort(__float2half_rn(y)) << 16);
}

// ================= converts =================
__global__ __launch_bounds__(256) void cvt2_kernel(
    const float* __restrict__ s0, __half* __restrict__ d0,
    const float* __restrict__ s1, __half* __restrict__ d1, int nb)
{
    const float* s = s0; __half* d = d0;
    int bx = blockIdx.x;
    if (bx >= nb) { s = s1; d = d1; bx -= nb; }
    int i = (bx * 256 + threadIdx.x) * 4;
    float4 v = *(const float4*)(s + i);
    uint2 uh;
    uh.x = pack_h2(v.x, v.y);
    uh.y = pack_h2(v.z, v.w);
    *(uint2*)(d + i) = uh;
}

__global__ __launch_bounds__(256) void wcvt_kernel(
    const float* __restrict__ w0, const float* __restrict__ w1,
    const float* __restrict__ w2, const float* __restrict__ w3,
    const float* __restrict__ w4, const float* __restrict__ w5,
    __half* __restrict__ hi)
{
    int i = (blockIdx.x * 256 + threadIdx.x) * 4;
    const float* src; int off;
    if      (i < W_SAOUT) { src = w0; off = W_SAIN; }
    else if (i < W_CAIN)  { src = w1; off = W_SAOUT; }
    else if (i < W_CAOUT) { src = w2; off = W_CAIN; }
    else if (i < W_LIN1)  { src = w3; off = W_CAOUT; }
    else if (i < W_LIN2)  { src = w4; off = W_LIN1; }
    else                  { src = w5; off = W_LIN2; }
    float4 v = *(const float4*)(src + (i - off));
    uint2 uh;
    uh.x = pack_h2(v.x, v.y);
    uh.y = pack_h2(v.z, v.w);
    *(uint2*)(hi + i) = uh;
}

// ================= mma.sync GEMM (fp16, BK=64, double-buffered fragments) =================
#define G_STAGE 32768
#define G_SMEM  (3 * G_STAGE)

__global__ __launch_bounds__(256, 2) void gemm_mma(
    const __half* __restrict__ A, const __half* __restrict__ B,
    const float* __restrict__ bias, __half* __restrict__ Oh,
    int N, int K, int act,
    const __half* A2, const __half* B2, const float* bias2,
    __half* Oh2, int N2, int nx1)
{
    extern __shared__ __align__(128) char smem[];
    const uint32_t sbase = smem_u32(smem);
    const int tid = threadIdx.x;
    const int lane = tid & 31, wid = tid >> 5;
    const int warp_m = wid & 3, warp_n = wid >> 2;

    int bx = blockIdx.x;
    if (A2 && bx >= nx1) {
        A = A2; B = B2; bias = bias2; Oh = Oh2; N = N2;
        bx -= nx1;
    }
    const int m0 = blockIdx.y * 128, n0 = bx * 128;

    float acc[2][8][4];
    #pragma unroll
    for (int t = 0; t < 2; t++)
        #pragma unroll
        for (int j = 0; j < 8; j++)
            #pragma unroll
            for (int e = 0; e < 4; e++) acc[t][j][e] = 0.0f;

    const int lrr = tid >> 3, lcc = tid & 7;
    uint32_t lsw[4];
    const __half* gA[4];
    const __half* gB[4];
    #pragma unroll
    for (int it = 0; it < 4; it++) {
        int r = lrr + it * 32;
        lsw[it] = r * 128 + ((lcc ^ (r & 7)) << 4);
        gA[it] = A + (size_t)(m0 + r) * K + lcc * 8;
        gB[it] = B + (size_t)(n0 + r) * K + lcc * 8;
    }

    auto stage_load = [&](int kk, int st) {
        const uint32_t sb = sbase + st * G_STAGE;
        #pragma unroll
        for (int it = 0; it < 4; it++)
            cp_async16(sb + lsw[it], gA[it] + kk);
        #pragma unroll
        for (int it = 0; it < 4; it++)
            cp_async16(sb + 16384 + lsw[it], gB[it] + kk);
        cp_commit();
    };

    const int lr = lane & 15;
    const int lseg = lane >> 4;
    uint32_t aoff[4][2], boff[4][4];
    #pragma unroll
    for (int kc = 0; kc < 4; kc++) {
        const int chunk = 2 * kc + lseg;
        #pragma unroll
        for (int t = 0; t < 2; t++) {
            int row = warp_m * 32 + t * 16 + lr;
            aoff[kc][t] = row * 128 + ((chunk ^ (row & 7)) << 4);
        }
        #pragma unroll
        for (int u = 0; u < 4; u++) {
            int row = warp_n * 64 + u * 16 + lr;
            boff[kc][u] = 16384 + row * 128 + ((chunk ^ (row & 7)) << 4);
        }
    }

    const int nch = K >> 6;
    stage_load(0, 0);
    stage_load(64, 1);

    for (int i = 0; i < nch; i++) {
        if (i < nch - 1) asm volatile("cp.async.wait_group 1;" ::: "memory");
        else             asm volatile("cp.async.wait_group 0;" ::: "memory");
        __syncthreads();
        if (i + 2 < nch) stage_load((i + 2) * 64, (i + 2) % 3);

        const uint32_t sb = sbase + (i % 3) * G_STAGE;
        uint32_t ah[2][2][4], bh[2][4][4];
        #pragma unroll
        for (int t = 0; t < 2; t++) ldsm_x4(ah[0][t], sb + aoff[0][t]);
        #pragma unroll
        for (int u = 0; u < 4; u++) ldsm_x4(bh[0][u], sb + boff[0][u]);

        #pragma unroll
        for (int kc = 0; kc < 4; kc++) {
            const int cur = kc & 1, nxt = cur ^ 1;
            if (kc < 3) {
                #pragma unroll
                for (int t = 0; t < 2; t++) ldsm_x4(ah[nxt][t], sb + aoff[kc + 1][t]);
                #pragma unroll
                for (int u = 0; u < 4; u++) ldsm_x4(bh[nxt][u], sb + boff[kc + 1][u]);
            }
            #pragma unroll
            for (int t = 0; t < 2; t++)
                #pragma unroll
                for (int u = 0; u < 4; u++) {
                    mma16816(acc[t][2 * u],     ah[cur][t], bh[cur][u][0], bh[cur][u][2]);
                    mma16816(acc[t][2 * u + 1], ah[cur][t], bh[cur][u][1], bh[cur][u][3]);
                }
        }
    }

    #pragma unroll
    for (int t = 0; t < 2; t++) {
        const int rbase = m0 + warp_m * 32 + t * 16 + (lane >> 2);
        #pragma unroll
        for (int j = 0; j < 8; j++) {
            const int col = n0 + warp_n * 64 + j * 8 + 2 * (lane & 3);
            const float b0 = __ldg(bias + col), b1 = __ldg(bias + col + 1);
            #pragma unroll
            for (int half = 0; half < 2; half++) {
                const int row = rbase + 8 * half;
                float v0 = acc[t][j][2 * half]     + b0;
                float v1 = acc[t][j][2 * half + 1] + b1;
                if (act) {
                    v0 = 0.5f * v0 * (1.0f + erff(v0 * 0.70710678118654752f));
                    v1 = 0.5f * v1 * (1.0f + erff(v1 * 0.70710678118654752f));
                }
                *(uint32_t*)(Oh + (size_t)row * N + col) = pack_h2(v0, v1);
            }
        }
    }
}

// ================= FA2-style attention (fp16, 64-query / 128-thread) =================
#define AT_BUF  16384
#define AT_SMEM (3 * AT_BUF)

__global__ __launch_bounds__(128) void attn_mma(
    const __half* __restrict__ Q, int ldq, int qoff,
    const __half* __restrict__ Kb, int ldk, int koff,
    const __half* __restrict__ Vb, int ldv, int voff,
    __half* __restrict__ Oh,
    const float* __restrict__ bias, float scale)
{
    extern __shared__ __align__(128) char smem[];
    const uint32_t sbase = smem_u32(smem);
    const int tid = threadIdx.x, lane = tid & 31, w = tid >> 5;
    const int qt = blockIdx.x, bh = blockIdx.y;
    const int b = bh & (BATCH - 1), h = bh >> 5;

    #pragma unroll
    for (int it = 0; it < 4; it++) {
        int idx = tid + it * 128, r = idx >> 3, c = idx & 7;
        uint32_t sw = r * 128 + ((c ^ (r & 7)) << 4);
        size_t g = (size_t)((qt * 64 + r) * BATCH + b) * ldq + qoff + h * HDIM + c * 8;
        cp_async16(sbase + sw, Q + g);
    }
    cp_commit();
    asm volatile("cp.async.wait_group 0;" ::: "memory");
    __syncthreads();

    const int lr = lane & 15, ls = lane >> 4;
    uint32_t qh[4][4];
    {
        int qrow = w * 16 + lr;
        #pragma unroll
        for (int kc = 0; kc < 4; kc++) {
            int chunk = 2 * kc + ls;
            uint32_t a = sbase + qrow * 128 + ((chunk ^ (qrow & 7)) << 4);
            ldsm_x4(qh[kc], a);
        }
    }
    __syncthreads();

    auto load_kt = [&](int kt, int st) {
        uint32_t sb = sbase + st * AT_BUF;
        #pragma unroll
        for (int it = 0; it < 4; it++) {
            int idx = tid + it * 128, r = idx >> 3, c = idx & 7;
            uint32_t sw = r * 128 + ((c ^ (r & 7)) << 4);
            size_t rowi = (size_t)((kt * 64 + r) * BATCH + b);
            cp_async16(sb + sw,        Kb + rowi * ldk + koff + h * HDIM + c * 8);
            cp_async16(sb + 8192 + sw, Vb + rowi * ldv + voff + h * HDIM + c * 8);
        }
        cp_commit();
    };
    load_kt(0, 0);
    load_kt(1, 1);

    float o[8][4];
    #pragma unroll
    for (int t = 0; t < 8; t++)
        #pragma unroll
        for (int e = 0; e < 4; e++) o[t][e] = 0.0f;
    float mrow0 = -1e30f, mrow1 = -1e30f, lsum0 = 0.0f, lsum1 = 0.0f;

    const int vkbase = ((lane & 16) ? 8 : 0) + (lane & 7);
    const int vcsel  = (lane >> 3) & 1;

    for (int kt = 0; kt < 8; kt++) {
        if (kt < 7) asm volatile("cp.async.wait_group 1;" ::: "memory");
        else        asm volatile("cp.async.wait_group 0;" ::: "memory");
        __syncthreads();
        if (kt + 2 < 8) load_kt(kt + 2, (kt + 2) % 3);
        const uint32_t sb = sbase + (kt % 3) * AT_BUF;

        float s[8][4];
        #pragma unroll
        for (int t = 0; t < 8; t++)
            #pragma unroll
            for (int e = 0; e < 4; e++) s[t][e] = 0.0f;
        #pragma unroll
        for (int kc = 0; kc < 4; kc++) {
            uint32_t kh[4][4];
            #pragma unroll
            for (int u = 0; u < 4; u++) {
                int krow = u * 16 + lr, chunk = 2 * kc + ls;
                uint32_t a = sb + krow * 128 + ((chunk ^ (krow & 7)) << 4);
                ldsm_x4(kh[u], a);
            }
            #pragma unroll
            for (int u = 0; u < 4; u++) {
                mma16816(s[2 * u],     qh[kc], kh[u][0], kh[u][2]);
                mma16816(s[2 * u + 1], qh[kc], kh[u][1], kh[u][3]);
            }
        }

        const int row0 = qt * 64 + w * 16 + (lane >> 2);
        if (bias) {
            #pragma unroll
            for (int t = 0; t < 8; t++) {
                int col = kt * 64 + t * 8 + 2 * (lane & 3);
                float2 b0 = *(const float2*)(bias + (size_t)row0 * TA + col);
                float2 b1 = *(const float2*)(bias + (size_t)(row0 + 8) * TA + col);
                s[t][0] = s[t][0] * scale + b0.x; s[t][1] = s[t][1] * scale + b0.y;
                s[t][2] = s[t][2] * scale + b1.x; s[t][3] = s[t][3] * scale + b1.y;
            }
        } else {
            #pragma unroll
            for (int t = 0; t < 8; t++)
                #pragma unroll
                for (int e = 0; e < 4; e++) s[t][e] *= scale;
        }

        float mx0 = -1e30f, mx1 = -1e30f;
        #pragma unroll
        for (int t = 0; t < 8; t++) {
            mx0 = fmaxf(mx0, fmaxf(s[t][0], s[t][1]));
            mx1 = fmaxf(mx1, fmaxf(s[t][2], s[t][3]));
        }
        mx0 = fmaxf(mx0, __shfl_xor_sync(0xffffffffu, mx0, 1));
        mx0 = fmaxf(mx0, __shfl_xor_sync(0xffffffffu, mx0, 2));
        mx1 = fmaxf(mx1, __shfl_xor_sync(0xffffffffu, mx1, 1));
        mx1 = fmaxf(mx1, __shfl_xor_sync(0xffffffffu, mx1, 2));
        float mn0 = fmaxf(mrow0, mx0), mn1 = fmaxf(mrow1, mx1);
        float a0 = __expf(mrow0 - mn0), a1 = __expf(mrow1 - mn1);
        mrow0 = mn0; mrow1 = mn1;

        float sum0 = 0.0f, sum1 = 0.0f;
        uint32_t phi[4][4];
        #pragma unroll
        for (int t = 0; t < 8; t++) {
            float p0 = __expf(s[t][0] - mn0), p1 = __expf(s[t][1] - mn0);
            float p2 = __expf(s[t][2] - mn1), p3 = __expf(s[t][3] - mn1);
            sum0 += p0 + p1; sum1 += p2 + p3;
            const int kc = t >> 1, j = (t & 1) * 2;
            phi[kc][j]     = pack_h2(p0, p1);
            phi[kc][j + 1] = pack_h2(p2, p3);
        }
        sum0 += __shfl_xor_sync(0xffffffffu, sum0, 1);
        sum0 += __shfl_xor_sync(0xffffffffu, sum0, 2);
        sum1 += __shfl_xor_sync(0xffffffffu, sum1, 1);
        sum1 += __shfl_xor_sync(0xffffffffu, sum1, 2);
        lsum0 = lsum0 * a0 + sum0;
        lsum1 = lsum1 * a1 + sum1;
        #pragma unroll
        for (int t = 0; t < 8; t++) {
            o[t][0] *= a0; o[t][1] *= a0;
            o[t][2] *= a1; o[t][3] *= a1;
        }

        #pragma unroll
        for (int kc = 0; kc < 4; kc++) {
            int vkey = kc * 16 + vkbase;
            uint32_t vh[4][4];
            #pragma unroll
            for (int du = 0; du < 4; du++) {
                int chunk = 2 * du + vcsel;
                uint32_t a = sb + 8192 + vkey * 128 + ((chunk ^ (vkey & 7)) << 4);
                ldsm_x4_t(vh[du], a);
            }
            #pragma unroll
            for (int du = 0; du < 4; du++) {
                mma16816(o[2 * du],     phi[kc], vh[du][0], vh[du][2]);
                mma16816(o[2 * du + 1], phi[kc], vh[du][1], vh[du][3]);
            }
        }
    }

    float inv0 = 1.0f / lsum0, inv1 = 1.0f / lsum1;
    const int row0 = qt * 64 + w * 16 + (lane >> 2);
    #pragma unroll
    for (int t = 0; t < 8; t++) {
        int col = t * 8 + 2 * (lane & 3);
        size_t off0 = (size_t)(row0 * BATCH + b) * D_MODEL + h * HDIM + col;
        size_t off1 = (size_t)((row0 + 8) * BATCH + b) * D_MODEL + h * HDIM + col;
        *(uint32_t*)(Oh + off0) = pack_h2(o[t][0] * inv0, o[t][1] * inv0);
        *(uint32_t*)(Oh + off1) = pack_h2(o[t][2] * inv1, o[t][3] * inv1);
    }
}

// ---------------- Bias precompute ----------------
__global__ void bias_kernel(const int* __restrict__ beats, float* __restrict__ out) {
    __shared__ int sb[NBEATS];
    int i = blockIdx.x;
    int j = threadIdx.x;
    if (threadIdx.x < NBEATS) sb[threadIdx.x] = beats[threadIdx.x];
    __syncthreads();
    float bb = 0.0f;
    #pragma unroll 8
    for (int n = 0; n < NBEATS; n++) {
        int bf = sb[n];
        if (j == bf) bb = fmaxf(bb, 2.0f);
        if (bf > 0      && j == bf - 1) bb = fmaxf(bb, 1.0f);
        if (bf < TA - 1 && j == bf + 1) bb = fmaxf(bb, 1.0f);
    }
    float scale = (float)(TA - 1) / (float)(TM - 1);
    float d = (float)i * scale - (float)j;
    out[i * TA + j] = -(d * d) * (1.0f / 32.0f) + bb;
}

// ---------------- Fused residual + LayerNorm (fp32 OR fp16 trunk in; fp32/fp16 out) ----------------
__global__ __launch_bounds__(256) void add_ln_kernel(
    const float* __restrict__ Af, const __half* __restrict__ Ah,
    const __half* __restrict__ Bv,
    const float* __restrict__ gatePtr,
    const float* __restrict__ gamma, const float* __restrict__ beta,
    float* __restrict__ outF, __half* __restrict__ outH)
{
    int t = blockIdx.x;
    int tid = threadIdx.x;
    float gscale = gatePtr ? tanhf(*gatePtr) : 1.0f;
    float a0, a1, a2, a3;
    if (Af) {
        float4 av = ((const float4*)(Af + (size_t)t * D_MODEL))[tid];
        a0 = av.x; a1 = av.y; a2 = av.z; a3 = av.w;
    } else {
        uint2 ua = ((const uint2*)(Ah + (size_t)t * D_MODEL))[tid];
        __half2 p01 = *(__half2*)&ua.x;
        __half2 p23 = *(__half2*)&ua.y;
        a0 = __low2float(p01); a1 = __high2float(p01);
        a2 = __low2float(p23); a3 = __high2float(p23);
    }
    uint2 ub = ((const uint2*)(Bv + (size_t)t * D_MODEL))[tid];
    __half2 h01 = *(__half2*)&ub.x;
    __half2 h23 = *(__half2*)&ub.y;
    float x0 = a0 + gscale * __low2float(h01);
    float x1 = a1 + gscale * __high2float(h01);
    float x2 = a2 + gscale * __low2float(h23);
    float x3 = a3 + gscale * __high2float(h23);
    float s  = x0 + x1 + x2 + x3;
    float ss = x0 * x0 + x1 * x1 + x2 * x2 + x3 * x3;

    __shared__ float rs[8], rss[8];
    #pragma unroll
    for (int o = 16; o > 0; o >>= 1) {
        s  += __shfl_xor_sync(0xffffffffu, s,  o);
        ss += __shfl_xor_sync(0xffffffffu, ss, o);
    }
    if ((tid & 31) == 0) { rs[tid >> 5] = s; rss[tid >> 5] = ss; }
    __syncthreads();
    float stot = 0.0f, sstot = 0.0f;
    #pragma unroll
    for (int i = 0; i < 8; i++) { stot += rs[i]; sstot += rss[i]; }
    float mean = stot * (1.0f / D_MODEL);
    float var  = sstot * (1.0f / D_MODEL) - mean * mean;
    float rstd = rsqrtf(var + LN_EPS);

    const float4* g4 = (const float4*)gamma;
    const float4* be4 = (const float4*)beta;
    float4 g = g4[tid], be = be4[tid];
    float4 o;
    o.x = (x0 - mean) * rstd * g.x + be.x;
    o.y = (x1 - mean) * rstd * g.y + be.y;
    o.z = (x2 - mean) * rstd * g.z + be.z;
    o.w = (x3 - mean) * rstd * g.w + be.w;
    if (outF) ((float4*)(outF + (size_t)t * D_MODEL))[tid] = o;
    if (outH) {
        uint2 uh;
        uh.x = pack_h2(o.x, o.y);
        uh.y = pack_h2(o.z, o.w);
        ((uint2*)(outH + (size_t)t * D_MODEL))[tid] = uh;
    }
}

// ---------------- Launch ----------------
extern "C" void kernel_launch(void* const* d_in, const int* in_sizes, int n_in,
                              void* d_out, int out_size) {
    const float* src      = (const float*)d_in[0];
    const float* audio    = (const float*)d_in[1];
    const int*   beats    = (const int*)  d_in[2];
    const float* sa_in_w  = (const float*)d_in[3];
    const float* sa_in_b  = (const float*)d_in[4];
    const float* sa_out_w = (const float*)d_in[5];
    const float* sa_out_b = (const float*)d_in[6];
    const float* ca_in_w  = (const float*)d_in[7];
    const float* ca_in_b  = (const float*)d_in[8];
    const float* ca_out_w = (const float*)d_in[9];
    const float* ca_out_b = (const float*)d_in[10];
    const float* gate     = (const float*)d_in[11];
    const float* n1_g     = (const float*)d_in[12];
    const float* n1_b     = (const float*)d_in[13];
    const float* nc_g     = (const float*)d_in[14];
    const float* nc_b     = (const float*)d_in[15];
    const float* n2_g     = (const float*)d_in[16];
    const float* n2_b     = (const float*)d_in[17];
    const float* lin1_w   = (const float*)d_in[18];
    const float* lin1_b   = (const float*)d_in[19];
    const float* lin2_w   = (const float*)d_in[20];
    const float* lin2_b   = (const float*)d_in[21];
    float* out = (float*)d_out;

    float *bias;
    __half *X, *AU, *TMP, *X1H, *X2H, *H, *W, *QKV, *KV, *CQ;
    cudaGetSymbolAddress((void**)&bias, g_bias);
    cudaGetSymbolAddress((void**)&X,    g_X);
    cudaGetSymbolAddress((void**)&AU,   g_AU);
    cudaGetSymbolAddress((void**)&TMP,  g_TMP);
    cudaGetSymbolAddress((void**)&X1H,  g_X1H);
    cudaGetSymbolAddress((void**)&X2H,  g_X2H);
    cudaGetSymbolAddress((void**)&H,    g_H);
    cudaGetSymbolAddress((void**)&W,    g_W);
    cudaGetSymbolAddress((void**)&QKV,  g_QKV);
    cudaGetSymbolAddress((void**)&KV,   g_KV);
    cudaGetSymbolAddress((void**)&CQ,   g_CQ);

    cudaFuncSetAttribute(gemm_mma, cudaFuncAttributeMaxDynamicSharedMemorySize, G_SMEM);
    cudaFuncSetAttribute(attn_mma, cudaFuncAttributeMaxDynamicSharedMemorySize, AT_SMEM);

    const int CVT_B = 256 * 4;
    #define H_NULL (__half*)nullptr
    #define F_NULL (float*)nullptr
    #define GEMM1(a, bw, bp, oh, Nn, Kk, act) \
        gemm_mma<<<dim3((Nn) / 128, NTOK / 128), 256, G_SMEM>>>( \
            a, bw, bp, oh, Nn, Kk, act, H_NULL, H_NULL, nullptr, H_NULL, 0, 0)

    // 0-2) bias, weights, src+audio converts (fused)
    bias_kernel<<<TM, TA>>>(beats, bias);
    wcvt_kernel<<<W_TOTAL / CVT_B, 256>>>(sa_in_w, sa_out_w, ca_in_w, ca_out_w,
                                          lin1_w, lin2_w, W);
    {
        const int nb = NTOK * D_MODEL / CVT_B;
        cvt2_kernel<<<2 * nb, 256>>>(src, X, audio, AU, nb);
    }

    // 3) fused: SA packed QKV (24 tiles) + CA KV-proj (16 tiles)
    gemm_mma<<<dim3(40, NTOK / 128), 256, G_SMEM>>>(
        X, W + W_SAIN, sa_in_b, QKV, 3 * D_MODEL, D_MODEL, 0,
        AU, W + W_CAIN + (size_t)D_MODEL * D_MODEL, ca_in_b + D_MODEL,
        KV, 2 * D_MODEL, 24);

    // 4) SA attention
    attn_mma<<<dim3(TM / 64, BATCH * NHEAD), 128, AT_SMEM>>>(
        QKV, 3 * D_MODEL, 0,
        QKV, 3 * D_MODEL, D_MODEL,
        QKV, 3 * D_MODEL, 2 * D_MODEL,
        X, nullptr, 0.125f);

    // 5) SA out-proj
    GEMM1(X, W + W_SAOUT, sa_out_b, TMP, D_MODEL, D_MODEL, 0);

    // 6) x1 = LN1(src + sa) -> fp16 trunk X1H
    add_ln_kernel<<<NTOK, 256>>>(src, H_NULL, TMP, nullptr, n1_g, n1_b, F_NULL, X1H);

    // 7) CA Q-proj (reads fp16 trunk)
    GEMM1(X1H, W + W_CAIN, ca_in_b, CQ, D_MODEL, D_MODEL, 0);

    // 8) CA attention (biased)
    attn_mma<<<dim3(TM / 64, BATCH * NHEAD), 128, AT_SMEM>>>(
        CQ, D_MODEL, 0,
        KV, 2 * D_MODEL, 0,
        KV, 2 * D_MODEL, D_MODEL,
        X, bias, 0.125f);

    // 9) CA out-proj
    GEMM1(X, W + W_CAOUT, ca_out_b, TMP, D_MODEL, D_MODEL, 0);

    // 10) x2 = LNc(x1 + tanh(gate)*cross) -> fp16 trunk X2H
    add_ln_kernel<<<NTOK, 256>>>(F_NULL, X1H, TMP, gate, nc_g, nc_b, F_NULL, X2H);

    // 11-12) FFN (reads fp16 trunk)
    GEMM1(X2H, W + W_LIN1, lin1_b, H, DFF, D_MODEL, 1);
    GEMM1(H, W + W_LIN2, lin2_b, TMP, D_MODEL, DFF, 0);

    // 13) out = LN2(x2 + ff) -> fp32 output
    add_ln_kernel<<<NTOK, 256>>>(F_NULL, X2H, TMP, nullptr, n2_g, n2_b, out, H_NULL);
}